// round 1
// baseline (speedup 1.0000x reference)
#include <cuda_runtime.h>
#include <cuda_bf16.h>
#include <cstdint>
#include <math.h>

// Problem constants
#define BATCH   2
#define SEQ     2048
#define HEADS   16
#define HDIM    128
#define HID     2048
#define NQKV    6144
#define BH      (BATCH * HEADS)      // 32
#define MROWS   (BATCH * SEQ)        // 4096

// scale * log2(e) folded into Q:  (1/sqrt(128)) * 1.4426950408889634
#define QSCALE  0.12751742f

// ---------------------------------------------------------------------------
// Scratch (static device globals; no allocation allowed)
// ---------------------------------------------------------------------------
__device__ float g_qkv[(size_t)MROWS * NQKV];            // 96 MB
__device__ float g_q[(size_t)BH * SEQ * HDIM];           // 32 MB
__device__ float g_k[(size_t)BH * SEQ * HDIM];           // 32 MB
__device__ float g_v[(size_t)BH * SEQ * HDIM];           // 32 MB
__device__ float g_attn[(size_t)MROWS * HID];            // 32 MB
__device__ float g_cos[SEQ * 64];
__device__ float g_sin[SEQ * 64];

// ---------------------------------------------------------------------------
// PTX helpers
// ---------------------------------------------------------------------------
__device__ __forceinline__ uint32_t f2tf32(float x) {
    uint32_t y;
    asm volatile("cvt.rna.tf32.f32 %0, %1;\n" : "=r"(y) : "f"(x));
    return y;
}
__device__ __forceinline__ float tf32r(float x) {
    return __uint_as_float(f2tf32(x));
}

__device__ __forceinline__ void mma_tf32(float c[4], const uint32_t a[4], const uint32_t b[2]) {
    asm volatile(
        "mma.sync.aligned.m16n8k8.row.col.f32.tf32.tf32.f32 "
        "{%0,%1,%2,%3}, {%4,%5,%6,%7}, {%8,%9}, {%0,%1,%2,%3};\n"
        : "+f"(c[0]), "+f"(c[1]), "+f"(c[2]), "+f"(c[3])
        : "r"(a[0]), "r"(a[1]), "r"(a[2]), "r"(a[3]), "r"(b[0]), "r"(b[1]));
}

__device__ __forceinline__ void cp_async16(float* smem_dst, const float* gmem_src) {
    unsigned sa = (unsigned)__cvta_generic_to_shared(smem_dst);
    asm volatile("cp.async.cg.shared.global [%0], [%1], 16;\n" :: "r"(sa), "l"(gmem_src) : "memory");
}
__device__ __forceinline__ void cp_async_commit() {
    asm volatile("cp.async.commit_group;\n" ::: "memory");
}
__device__ __forceinline__ void cp_async_wait_all() {
    asm volatile("cp.async.wait_group 0;\n" ::: "memory");
}

// ---------------------------------------------------------------------------
// Kernel 0: trig tables (fp64 for accuracy at large angles)
// ---------------------------------------------------------------------------
__global__ void trig_init_kernel() {
    int idx = blockIdx.x * blockDim.x + threadIdx.x;   // SEQ*64 total
    if (idx >= SEQ * 64) return;
    int s  = idx >> 6;
    int d2 = idx & 63;
    double inv = exp(-(double)d2 * (9.210340371976184 / 64.0));  // 10000^(-d2/64)
    double ang = (double)s * inv;
    double cs, sn;
    sincos(ang, &sn, &cs);
    g_cos[idx] = (float)cs;
    g_sin[idx] = (float)sn;
}

// ---------------------------------------------------------------------------
// Kernel 1/4: generic tf32 GEMM:  C[m,n] = sum_k A[m,k] * B[n,k] + bias[n]
// A: [M,K] row-major, B: [N,K] row-major. Tiles 128x128x32, 256 threads,
// cp.async double buffer.
// ---------------------------------------------------------------------------
#define GBK 32
#define GSTRIDE 36   // 32 + 4 pad (floats)

__global__ __launch_bounds__(256) void gemm_tf32_kernel(
    const float* __restrict__ A, const float* __restrict__ B,
    const float* __restrict__ bias, float* __restrict__ C,
    int M, int N, int K)
{
    extern __shared__ float sm[];
    // layout: As[2][128*36], Bs[2][128*36]
    const int STG = 128 * GSTRIDE;   // 4608 floats per stage per matrix
    float* Asm = sm;                 // 2 stages
    float* Bsm = sm + 2 * STG;

    int tid  = threadIdx.x;
    int bm   = blockIdx.y;
    int bn   = blockIdx.x;
    int lane = tid & 31;
    int wid  = tid >> 5;
    int wm   = wid >> 2;       // 0..1
    int wn   = wid & 3;        // 0..3

    const float* Ab = A + (size_t)bm * 128 * K;
    const float* Bb = B + (size_t)bn * 128 * K;

    int lr = tid >> 3;         // 0..31 (row within a 32-row pass)
    int lc = (tid & 7) * 4;    // float col (0..28)

    int KT = K / GBK;

    // prologue: stage 0
    {
        const float* Ag = Ab;
        const float* Bg = Bb;
        float* as = Asm;
        float* bs = Bsm;
        #pragma unroll
        for (int p = 0; p < 4; p++) {
            int r = p * 32 + lr;
            cp_async16(as + r * GSTRIDE + lc, Ag + (size_t)r * K + lc);
            cp_async16(bs + r * GSTRIDE + lc, Bg + (size_t)r * K + lc);
        }
        cp_async_commit();
    }
    cp_async_wait_all();
    __syncthreads();

    float acc[4][4][4];
    #pragma unroll
    for (int i = 0; i < 4; i++)
        #pragma unroll
        for (int j = 0; j < 4; j++)
            #pragma unroll
            for (int k = 0; k < 4; k++) acc[i][j][k] = 0.0f;

    for (int kt = 0; kt < KT; kt++) {
        int cur = kt & 1;
        if (kt + 1 < KT) {
            int nxt = (kt + 1) & 1;
            const float* Ag = Ab + (size_t)(kt + 1) * GBK;
            const float* Bg = Bb + (size_t)(kt + 1) * GBK;
            float* as = Asm + nxt * STG;
            float* bs = Bsm + nxt * STG;
            #pragma unroll
            for (int p = 0; p < 4; p++) {
                int r = p * 32 + lr;
                cp_async16(as + r * GSTRIDE + lc, Ag + (size_t)r * K + lc);
                cp_async16(bs + r * GSTRIDE + lc, Bg + (size_t)r * K + lc);
            }
            cp_async_commit();
        }

        const float* as = Asm + cur * STG;
        const float* bs = Bsm + cur * STG;

        #pragma unroll
        for (int ks = 0; ks < 4; ks++) {
            int kb = ks * 8 + (lane & 3);
            uint32_t af[4][4];
            #pragma unroll
            for (int mt = 0; mt < 4; mt++) {
                int r = wm * 64 + mt * 16 + (lane >> 2);
                af[mt][0] = f2tf32(as[r * GSTRIDE + kb]);
                af[mt][1] = f2tf32(as[(r + 8) * GSTRIDE + kb]);
                af[mt][2] = f2tf32(as[r * GSTRIDE + kb + 4]);
                af[mt][3] = f2tf32(as[(r + 8) * GSTRIDE + kb + 4]);
            }
            #pragma unroll
            for (int nt = 0; nt < 4; nt++) {
                int cc = wn * 32 + nt * 8 + (lane >> 2);
                uint32_t bf[2];
                bf[0] = f2tf32(bs[cc * GSTRIDE + kb]);
                bf[1] = f2tf32(bs[cc * GSTRIDE + kb + 4]);
                #pragma unroll
                for (int mt = 0; mt < 4; mt++) mma_tf32(acc[mt][nt], af[mt], bf);
            }
        }

        cp_async_wait_all();
        __syncthreads();
    }

    // epilogue
    #pragma unroll
    for (int mt = 0; mt < 4; mt++) {
        int r = bm * 128 + wm * 64 + mt * 16 + (lane >> 2);
        #pragma unroll
        for (int nt = 0; nt < 4; nt++) {
            int c = bn * 128 + wn * 32 + nt * 8 + (lane & 3) * 2;
            float b0 = bias[c], b1 = bias[c + 1];
            C[(size_t)r * N + c]           = acc[mt][nt][0] + b0;
            C[(size_t)r * N + c + 1]       = acc[mt][nt][1] + b1;
            C[(size_t)(r + 8) * N + c]     = acc[mt][nt][2] + b0;
            C[(size_t)(r + 8) * N + c + 1] = acc[mt][nt][3] + b1;
        }
    }
}

// ---------------------------------------------------------------------------
// Kernel 2: RoPE + scatter qkv -> g_q (scaled tf32-friendly later), g_k, g_v
// One thread per (b, s, h, d2) pair, d2 in [0,64)
// ---------------------------------------------------------------------------
__global__ __launch_bounds__(256) void rope_scatter_kernel() {
    int idx = blockIdx.x * blockDim.x + threadIdx.x;   // MROWS*HEADS*64 = 4194304
    int d2 = idx & 63;
    int h  = (idx >> 6) & 15;
    int s  = (idx >> 10) & 2047;
    int b  = idx >> 21;

    size_t row = (size_t)b * SEQ + s;
    const float* base = g_qkv + row * NQKV + (size_t)h * HDIM;

    float cs = g_cos[s * 64 + d2];
    float sn = g_sin[s * 64 + d2];

    float q1 = base[d2],          q2 = base[d2 + 64];
    float k1 = base[HID + d2],    k2 = base[HID + d2 + 64];
    float v1 = base[2*HID + d2],  v2 = base[2*HID + d2 + 64];

    int bh = b * HEADS + h;
    size_t o = ((size_t)bh * SEQ + s) * HDIM;
    g_q[o + d2]      = q1 * cs - q2 * sn;
    g_q[o + d2 + 64] = q2 * cs + q1 * sn;
    g_k[o + d2]      = k1 * cs - k2 * sn;
    g_k[o + d2 + 64] = k2 * cs + k1 * sn;
    g_v[o + d2]      = v1;
    g_v[o + d2 + 64] = v2;
}

// ---------------------------------------------------------------------------
// Kernel 3: causal flash attention, Br=Bc=64, 4 warps, tf32 mma
// grid = (32 qtiles, 32 bh), block = 128
// smem: Qs[64][132] Ks[64][132] Vs[64][132] Ps[64][68]
// ---------------------------------------------------------------------------
#define ASTRIDE 132
#define PSTRIDE 68

__global__ __launch_bounds__(128) void attn_kernel() {
    extern __shared__ float sm[];
    float* Qs = sm;
    float* Ks = Qs + 64 * ASTRIDE;
    float* Vs = Ks + 64 * ASTRIDE;
    float* Ps = Vs + 64 * ASTRIDE;

    int tid  = threadIdx.x;
    int warp = tid >> 5;
    int lane = tid & 31;
    int qi   = blockIdx.x;
    int bh   = blockIdx.y;

    // load Q tile (scaled by QSCALE, rounded to tf32)
    {
        const float* Qg = g_q + ((size_t)bh * SEQ + (size_t)qi * 64) * HDIM;
        for (int i = tid; i < 64 * 32; i += 128) {
            int r = i >> 5;
            int c = (i & 31) * 4;
            float4 v = *(const float4*)(Qg + (size_t)r * HDIM + c);
            float* dst = Qs + r * ASTRIDE + c;
            dst[0] = tf32r(v.x * QSCALE);
            dst[1] = tf32r(v.y * QSCALE);
            dst[2] = tf32r(v.z * QSCALE);
            dst[3] = tf32r(v.w * QSCALE);
        }
    }

    int r0 = warp * 16 + (lane >> 2);   // local row for c0/c1 (c2/c3 -> r0+8)

    float m0 = -1e30f, m1 = -1e30f;
    float l0 = 0.0f,   l1 = 0.0f;
    float acc[16][4];
    #pragma unroll
    for (int i = 0; i < 16; i++)
        #pragma unroll
        for (int j = 0; j < 4; j++) acc[i][j] = 0.0f;

    for (int kt = 0; kt <= qi; kt++) {
        __syncthreads();   // protect Ks/Vs reuse (also orders Q load on iter 0)
        {
            const float* Kg = g_k + ((size_t)bh * SEQ + (size_t)kt * 64) * HDIM;
            const float* Vg = g_v + ((size_t)bh * SEQ + (size_t)kt * 64) * HDIM;
            for (int i = tid; i < 64 * 32; i += 128) {
                int r = i >> 5;
                int c = (i & 31) * 4;
                float4 kv = *(const float4*)(Kg + (size_t)r * HDIM + c);
                float4 vv = *(const float4*)(Vg + (size_t)r * HDIM + c);
                float* kd = Ks + r * ASTRIDE + c;
                float* vd = Vs + r * ASTRIDE + c;
                kd[0] = tf32r(kv.x); kd[1] = tf32r(kv.y);
                kd[2] = tf32r(kv.z); kd[3] = tf32r(kv.w);
                vd[0] = tf32r(vv.x); vd[1] = tf32r(vv.y);
                vd[2] = tf32r(vv.z); vd[3] = tf32r(vv.w);
            }
        }
        __syncthreads();

        // ---- S = Q K^T (16x64 per warp) ----
        float sc[8][4];
        #pragma unroll
        for (int nt = 0; nt < 8; nt++)
            #pragma unroll
            for (int j = 0; j < 4; j++) sc[nt][j] = 0.0f;

        #pragma unroll
        for (int ks = 0; ks < 16; ks++) {
            int kb = ks * 8 + (lane & 3);
            uint32_t a[4];
            a[0] = __float_as_uint(Qs[r0 * ASTRIDE + kb]);
            a[1] = __float_as_uint(Qs[(r0 + 8) * ASTRIDE + kb]);
            a[2] = __float_as_uint(Qs[r0 * ASTRIDE + kb + 4]);
            a[3] = __float_as_uint(Qs[(r0 + 8) * ASTRIDE + kb + 4]);
            #pragma unroll
            for (int nt = 0; nt < 8; nt++) {
                int n = nt * 8 + (lane >> 2);
                uint32_t bfr[2];
                bfr[0] = __float_as_uint(Ks[n * ASTRIDE + kb]);
                bfr[1] = __float_as_uint(Ks[n * ASTRIDE + kb + 4]);
                mma_tf32(sc[nt], a, bfr);
            }
        }

        // ---- causal mask on diagonal tile ----
        if (kt == qi) {
            #pragma unroll
            for (int nt = 0; nt < 8; nt++) {
                int cb = nt * 8 + (lane & 3) * 2;
                if (cb     > r0)     sc[nt][0] = -1e30f;
                if (cb + 1 > r0)     sc[nt][1] = -1e30f;
                if (cb     > r0 + 8) sc[nt][2] = -1e30f;
                if (cb + 1 > r0 + 8) sc[nt][3] = -1e30f;
            }
        }

        // ---- online softmax (base 2, scale already folded into Q) ----
        float rx0 = -1e30f, rx1 = -1e30f;
        #pragma unroll
        for (int nt = 0; nt < 8; nt++) {
            rx0 = fmaxf(rx0, fmaxf(sc[nt][0], sc[nt][1]));
            rx1 = fmaxf(rx1, fmaxf(sc[nt][2], sc[nt][3]));
        }
        rx0 = fmaxf(rx0, __shfl_xor_sync(0xffffffffu, rx0, 1));
        rx0 = fmaxf(rx0, __shfl_xor_sync(0xffffffffu, rx0, 2));
        rx1 = fmaxf(rx1, __shfl_xor_sync(0xffffffffu, rx1, 1));
        rx1 = fmaxf(rx1, __shfl_xor_sync(0xffffffffu, rx1, 2));

        float mn0 = fmaxf(m0, rx0);
        float mn1 = fmaxf(m1, rx1);
        float al0 = exp2f(m0 - mn0);
        float al1 = exp2f(m1 - mn1);

        float s0 = 0.0f, s1 = 0.0f;
        #pragma unroll
        for (int nt = 0; nt < 8; nt++) {
            sc[nt][0] = exp2f(sc[nt][0] - mn0);
            sc[nt][1] = exp2f(sc[nt][1] - mn0);
            sc[nt][2] = exp2f(sc[nt][2] - mn1);
            sc[nt][3] = exp2f(sc[nt][3] - mn1);
            s0 += sc[nt][0] + sc[nt][1];
            s1 += sc[nt][2] + sc[nt][3];
        }
        s0 += __shfl_xor_sync(0xffffffffu, s0, 1);
        s0 += __shfl_xor_sync(0xffffffffu, s0, 2);
        s1 += __shfl_xor_sync(0xffffffffu, s1, 1);
        s1 += __shfl_xor_sync(0xffffffffu, s1, 2);

        l0 = l0 * al0 + s0;
        l1 = l1 * al1 + s1;
        m0 = mn0;
        m1 = mn1;

        #pragma unroll
        for (int nt = 0; nt < 16; nt++) {
            acc[nt][0] *= al0; acc[nt][1] *= al0;
            acc[nt][2] *= al1; acc[nt][3] *= al1;
        }

        // ---- write P to smem (own rows only) ----
        #pragma unroll
        for (int nt = 0; nt < 8; nt++) {
            int c = nt * 8 + (lane & 3) * 2;
            Ps[r0 * PSTRIDE + c]           = tf32r(sc[nt][0]);
            Ps[r0 * PSTRIDE + c + 1]       = tf32r(sc[nt][1]);
            Ps[(r0 + 8) * PSTRIDE + c]     = tf32r(sc[nt][2]);
            Ps[(r0 + 8) * PSTRIDE + c + 1] = tf32r(sc[nt][3]);
        }
        __syncwarp();

        // ---- O += P @ V ----
        #pragma unroll
        for (int ks = 0; ks < 8; ks++) {
            int kb = ks * 8 + (lane & 3);
            uint32_t a[4];
            a[0] = __float_as_uint(Ps[r0 * PSTRIDE + kb]);
            a[1] = __float_as_uint(Ps[(r0 + 8) * PSTRIDE + kb]);
            a[2] = __float_as_uint(Ps[r0 * PSTRIDE + kb + 4]);
            a[3] = __float_as_uint(Ps[(r0 + 8) * PSTRIDE + kb + 4]);
            #pragma unroll
            for (int nt = 0; nt < 16; nt++) {
                int c = nt * 8 + (lane >> 2);
                uint32_t bfr[2];
                bfr[0] = __float_as_uint(Vs[kb * ASTRIDE + c]);
                bfr[1] = __float_as_uint(Vs[(kb + 4) * ASTRIDE + c]);
                mma_tf32(acc[nt], a, bfr);
            }
        }
    }

    // epilogue: normalize and write to g_attn[B,S,HID] (transposed head layout)
    float inv0 = 1.0f / l0;
    float inv1 = 1.0f / l1;
    int b = bh >> 4;
    int h = bh & 15;
    size_t rowg = (size_t)b * SEQ + (size_t)qi * 64 + r0;
    float* out0 = g_attn + rowg * HID + (size_t)h * HDIM;
    float* out1 = out0 + (size_t)8 * HID;
    #pragma unroll
    for (int nt = 0; nt < 16; nt++) {
        int c = nt * 8 + (lane & 3) * 2;
        out0[c]     = acc[nt][0] * inv0;
        out0[c + 1] = acc[nt][1] * inv0;
        out1[c]     = acc[nt][2] * inv1;
        out1[c + 1] = acc[nt][3] * inv1;
    }
}

// ---------------------------------------------------------------------------
// Host launcher
// ---------------------------------------------------------------------------
extern "C" void kernel_launch(void* const* d_in, const int* in_sizes, int n_in,
                              void* d_out, int out_size)
{
    const float* hs      = (const float*)d_in[0];
    const float* w_qkv   = (const float*)d_in[1];
    const float* b_qkv   = (const float*)d_in[2];
    const float* w_dense = (const float*)d_in[3];
    const float* b_dense = (const float*)d_in[4];
    float* out = (float*)d_out;

    float *p_qkv, *p_attn;
    cudaGetSymbolAddress((void**)&p_qkv, g_qkv);
    cudaGetSymbolAddress((void**)&p_attn, g_attn);

    const int gemm_smem = 2 * 2 * 128 * GSTRIDE * (int)sizeof(float);          // 73728
    const int attn_smem = (3 * 64 * ASTRIDE + 64 * PSTRIDE) * (int)sizeof(float); // 118784
    cudaFuncSetAttribute(gemm_tf32_kernel, cudaFuncAttributeMaxDynamicSharedMemorySize, gemm_smem);
    cudaFuncSetAttribute(attn_kernel, cudaFuncAttributeMaxDynamicSharedMemorySize, attn_smem);

    // 0) trig tables
    trig_init_kernel<<<(SEQ * 64 + 255) / 256, 256>>>();

    // 1) QKV GEMM: [4096,2048] x [6144,2048]^T -> [4096,6144]
    gemm_tf32_kernel<<<dim3(NQKV / 128, MROWS / 128), 256, gemm_smem>>>(
        hs, w_qkv, b_qkv, p_qkv, MROWS, NQKV, HID);

    // 2) RoPE + scatter
    rope_scatter_kernel<<<(MROWS * HEADS * 64) / 256, 256>>>();

    // 3) causal flash attention
    attn_kernel<<<dim3(SEQ / 64, BH), 128, attn_smem>>>();

    // 4) dense GEMM: [4096,2048] x [2048,2048]^T -> [4096,2048]
    gemm_tf32_kernel<<<dim3(HID / 128, MROWS / 128), 256, gemm_smem>>>(
        p_attn, w_dense, b_dense, out, MROWS, HID, HID);
}

// round 2
// speedup vs baseline: 1.2109x; 1.2109x over previous
#include <cuda_runtime.h>
#include <cuda_bf16.h>
#include <cstdint>
#include <math.h>

// Problem constants
#define BATCH   2
#define SEQ     2048
#define HEADS   16
#define HDIM    128
#define HID     2048
#define NQKV    6144
#define BH      (BATCH * HEADS)      // 32
#define MROWS   (BATCH * SEQ)        // 4096

// scale * log2(e) folded into Q:  (1/sqrt(128)) * 1.4426950408889634
#define QSCALE  0.12751742f

// ---------------------------------------------------------------------------
// Scratch (static device globals; no allocation allowed)
// ---------------------------------------------------------------------------
__device__ float g_qkv[(size_t)MROWS * NQKV];            // 96 MB
__device__ float g_q[(size_t)BH * SEQ * HDIM];           // 32 MB (tf32-rounded, scaled)
__device__ float g_k[(size_t)BH * SEQ * HDIM];           // 32 MB (tf32-rounded)
__device__ float g_v[(size_t)BH * SEQ * HDIM];           // 32 MB (tf32-rounded)
__device__ float g_attn[(size_t)MROWS * HID];            // 32 MB (tf32-rounded)
__device__ float g_hst[(size_t)MROWS * HID];             // 32 MB (tf32 hs)
__device__ float g_wqkvt[(size_t)NQKV * HID];            // 48 MB (tf32 w_qkv)
__device__ float g_wdt[(size_t)HID * HID];               // 16 MB (tf32 w_dense)
__device__ float g_cos[SEQ * 64];
__device__ float g_sin[SEQ * 64];

// ---------------------------------------------------------------------------
// PTX helpers
// ---------------------------------------------------------------------------
__device__ __forceinline__ uint32_t f2tf32(float x) {
    uint32_t y;
    asm volatile("cvt.rna.tf32.f32 %0, %1;\n" : "=r"(y) : "f"(x));
    return y;
}
__device__ __forceinline__ float tf32r(float x) {
    return __uint_as_float(f2tf32(x));
}

__device__ __forceinline__ void mma_tf32(float c[4], const uint32_t a[4], const uint32_t b[2]) {
    asm volatile(
        "mma.sync.aligned.m16n8k8.row.col.f32.tf32.tf32.f32 "
        "{%0,%1,%2,%3}, {%4,%5,%6,%7}, {%8,%9}, {%0,%1,%2,%3};\n"
        : "+f"(c[0]), "+f"(c[1]), "+f"(c[2]), "+f"(c[3])
        : "r"(a[0]), "r"(a[1]), "r"(a[2]), "r"(a[3]), "r"(b[0]), "r"(b[1]));
}

__device__ __forceinline__ void cp_async16(float* smem_dst, const float* gmem_src) {
    unsigned sa = (unsigned)__cvta_generic_to_shared(smem_dst);
    asm volatile("cp.async.cg.shared.global [%0], [%1], 16;\n" :: "r"(sa), "l"(gmem_src) : "memory");
}
__device__ __forceinline__ void cp_async_commit() {
    asm volatile("cp.async.commit_group;\n" ::: "memory");
}

// ---------------------------------------------------------------------------
// Kernel: trig tables (fp64 for accuracy at large angles)
// ---------------------------------------------------------------------------
__global__ void trig_init_kernel() {
    int idx = blockIdx.x * blockDim.x + threadIdx.x;   // SEQ*64 total
    if (idx >= SEQ * 64) return;
    int s  = idx >> 6;
    int d2 = idx & 63;
    double inv = exp(-(double)d2 * (9.210340371976184 / 64.0));  // 10000^(-d2/64)
    double ang = (double)s * inv;
    double cs, sn;
    sincos(ang, &sn, &cs);
    g_cos[idx] = (float)cs;
    g_sin[idx] = (float)sn;
}

// ---------------------------------------------------------------------------
// Kernel: elementwise tf32 pre-round (float4 vectorized)
// ---------------------------------------------------------------------------
__global__ __launch_bounds__(256) void cvt_tf32_kernel(const float* __restrict__ src,
                                                       float* __restrict__ dst, int n4) {
    int i = blockIdx.x * blockDim.x + threadIdx.x;
    if (i >= n4) return;
    float4 v = ((const float4*)src)[i];
    v.x = tf32r(v.x); v.y = tf32r(v.y); v.z = tf32r(v.z); v.w = tf32r(v.w);
    ((float4*)dst)[i] = v;
}

// ---------------------------------------------------------------------------
// tf32 GEMM:  C[m,n] = sum_k A[m,k]*B[n,k] + bias[n]
// A,B already tf32-pre-rounded. Tiles 128x128x32, 256 threads, cp.async 2-stage.
// ---------------------------------------------------------------------------
#define GBK 32
#define GSTRIDE 36   // 32 + 4 pad (floats)

__global__ __launch_bounds__(256) void gemm_tf32_kernel(
    const float* __restrict__ A, const float* __restrict__ B,
    const float* __restrict__ bias, float* __restrict__ C,
    int M, int N, int K)
{
    extern __shared__ float sm[];
    const int STG = 128 * GSTRIDE;
    float* Asm = sm;
    float* Bsm = sm + 2 * STG;

    int tid  = threadIdx.x;
    int bm   = blockIdx.y;
    int bn   = blockIdx.x;
    int lane = tid & 31;
    int wid  = tid >> 5;
    int wm   = wid >> 2;
    int wn   = wid & 3;

    const float* Ab = A + (size_t)bm * 128 * K;
    const float* Bb = B + (size_t)bn * 128 * K;

    int lr = tid >> 3;
    int lc = (tid & 7) * 4;

    int KT = K / GBK;

    {
        #pragma unroll
        for (int p = 0; p < 4; p++) {
            int r = p * 32 + lr;
            cp_async16(Asm + r * GSTRIDE + lc, Ab + (size_t)r * K + lc);
            cp_async16(Bsm + r * GSTRIDE + lc, Bb + (size_t)r * K + lc);
        }
        cp_async_commit();
    }
    asm volatile("cp.async.wait_group 0;\n" ::: "memory");
    __syncthreads();

    float acc[4][4][4];
    #pragma unroll
    for (int i = 0; i < 4; i++)
        #pragma unroll
        for (int j = 0; j < 4; j++)
            #pragma unroll
            for (int k = 0; k < 4; k++) acc[i][j][k] = 0.0f;

    for (int kt = 0; kt < KT; kt++) {
        int cur = kt & 1;
        if (kt + 1 < KT) {
            int nxt = (kt + 1) & 1;
            const float* Ag = Ab + (size_t)(kt + 1) * GBK;
            const float* Bg = Bb + (size_t)(kt + 1) * GBK;
            float* as = Asm + nxt * STG;
            float* bs = Bsm + nxt * STG;
            #pragma unroll
            for (int p = 0; p < 4; p++) {
                int r = p * 32 + lr;
                cp_async16(as + r * GSTRIDE + lc, Ag + (size_t)r * K + lc);
                cp_async16(bs + r * GSTRIDE + lc, Bg + (size_t)r * K + lc);
            }
            cp_async_commit();
        }

        const float* as = Asm + cur * STG;
        const float* bs = Bsm + cur * STG;

        #pragma unroll
        for (int ks = 0; ks < 4; ks++) {
            int kb = ks * 8 + (lane & 3);
            uint32_t af[4][4];
            #pragma unroll
            for (int mt = 0; mt < 4; mt++) {
                int r = wm * 64 + mt * 16 + (lane >> 2);
                af[mt][0] = __float_as_uint(as[r * GSTRIDE + kb]);
                af[mt][1] = __float_as_uint(as[(r + 8) * GSTRIDE + kb]);
                af[mt][2] = __float_as_uint(as[r * GSTRIDE + kb + 4]);
                af[mt][3] = __float_as_uint(as[(r + 8) * GSTRIDE + kb + 4]);
            }
            #pragma unroll
            for (int nt = 0; nt < 4; nt++) {
                int cc = wn * 32 + nt * 8 + (lane >> 2);
                uint32_t bf[2];
                bf[0] = __float_as_uint(bs[cc * GSTRIDE + kb]);
                bf[1] = __float_as_uint(bs[cc * GSTRIDE + kb + 4]);
                #pragma unroll
                for (int mt = 0; mt < 4; mt++) mma_tf32(acc[mt][nt], af[mt], bf);
            }
        }

        if (kt + 1 < KT) {
            asm volatile("cp.async.wait_group 0;\n" ::: "memory");
        }
        __syncthreads();
    }

    #pragma unroll
    for (int mt = 0; mt < 4; mt++) {
        int r = bm * 128 + wm * 64 + mt * 16 + (lane >> 2);
        #pragma unroll
        for (int nt = 0; nt < 4; nt++) {
            int c = bn * 128 + wn * 32 + nt * 8 + (lane & 3) * 2;
            float b0 = bias[c], b1 = bias[c + 1];
            C[(size_t)r * N + c]           = acc[mt][nt][0] + b0;
            C[(size_t)r * N + c + 1]       = acc[mt][nt][1] + b1;
            C[(size_t)(r + 8) * N + c]     = acc[mt][nt][2] + b0;
            C[(size_t)(r + 8) * N + c + 1] = acc[mt][nt][3] + b1;
        }
    }
}

// ---------------------------------------------------------------------------
// Kernel: RoPE + scatter qkv -> g_q (scaled, tf32), g_k (tf32), g_v (tf32)
// ---------------------------------------------------------------------------
__global__ __launch_bounds__(256) void rope_scatter_kernel() {
    int idx = blockIdx.x * blockDim.x + threadIdx.x;   // MROWS*HEADS*64
    int d2 = idx & 63;
    int h  = (idx >> 6) & 15;
    int s  = (idx >> 10) & 2047;
    int b  = idx >> 21;

    size_t row = (size_t)b * SEQ + s;
    const float* base = g_qkv + row * NQKV + (size_t)h * HDIM;

    float cs = g_cos[s * 64 + d2];
    float sn = g_sin[s * 64 + d2];

    float q1 = base[d2],          q2 = base[d2 + 64];
    float k1 = base[HID + d2],    k2 = base[HID + d2 + 64];
    float v1 = base[2*HID + d2],  v2 = base[2*HID + d2 + 64];

    int bh = b * HEADS + h;
    size_t o = ((size_t)bh * SEQ + s) * HDIM;
    g_q[o + d2]      = tf32r((q1 * cs - q2 * sn) * QSCALE);
    g_q[o + d2 + 64] = tf32r((q2 * cs + q1 * sn) * QSCALE);
    g_k[o + d2]      = tf32r(k1 * cs - k2 * sn);
    g_k[o + d2 + 64] = tf32r(k2 * cs + k1 * sn);
    g_v[o + d2]      = tf32r(v1);
    g_v[o + d2 + 64] = tf32r(v2);
}

// ---------------------------------------------------------------------------
// Causal flash attention: Br=128, Bc=64, 8 warps, tf32 mma
// Q fragments in registers; K/V double-buffered via cp.async.
// grid = (16 qtiles [reversed], 32 bh), block = 256
// smem: Ks[2][64][132], Vs[2][64][132], Ps[128][68]  = 169984 B
// ---------------------------------------------------------------------------
#define BR 128
#define BC 64
#define KSTRIDE 132
#define PSTRIDE 68
#define KVST (64 * KSTRIDE)

__global__ __launch_bounds__(256, 1) void attn_kernel() {
    extern __shared__ float sm[];
    float* Ps = sm + 4 * KVST;

    int tid  = threadIdx.x;
    int warp = tid >> 5;
    int lane = tid & 31;
    int qi   = gridDim.x - 1 - blockIdx.x;   // big tiles first
    int bh   = blockIdx.y;

    const float* Qg = g_q + ((size_t)bh * SEQ + (size_t)qi * BR) * HDIM;
    const float* Kg = g_k + (size_t)bh * SEQ * HDIM;
    const float* Vg = g_v + (size_t)bh * SEQ * HDIM;

    int r0 = warp * 16 + (lane >> 2);   // local row (c0/c1); c2/c3 -> r0+8

    // ---- Q fragments to registers (once) ----
    uint32_t qf[16][4];
    #pragma unroll
    for (int ks = 0; ks < 16; ks++) {
        int kb = ks * 8 + (lane & 3);
        qf[ks][0] = __float_as_uint(__ldg(Qg + (size_t)r0 * HDIM + kb));
        qf[ks][1] = __float_as_uint(__ldg(Qg + (size_t)(r0 + 8) * HDIM + kb));
        qf[ks][2] = __float_as_uint(__ldg(Qg + (size_t)r0 * HDIM + kb + 4));
        qf[ks][3] = __float_as_uint(__ldg(Qg + (size_t)(r0 + 8) * HDIM + kb + 4));
    }

    int ktmax = 2 * qi + 1;

    // prologue: tile 0 -> buffer 0
    {
        float* kd = sm;
        float* vd = sm + 2 * KVST;
        for (int i = tid; i < 2048; i += 256) {
            int r = i >> 5;
            int c = (i & 31) * 4;
            cp_async16(kd + r * KSTRIDE + c, Kg + (size_t)r * HDIM + c);
            cp_async16(vd + r * KSTRIDE + c, Vg + (size_t)r * HDIM + c);
        }
        cp_async_commit();
    }

    float m0 = -1e30f, m1 = -1e30f;
    float l0 = 0.0f,   l1 = 0.0f;
    float acc[16][4];
    #pragma unroll
    for (int i = 0; i < 16; i++)
        #pragma unroll
        for (int j = 0; j < 4; j++) acc[i][j] = 0.0f;

    for (int kt = 0; kt <= ktmax; kt++) {
        int cur = kt & 1;
        if (kt < ktmax) {
            int nb = cur ^ 1;
            const float* kp = Kg + (size_t)(kt + 1) * BC * HDIM;
            const float* vp = Vg + (size_t)(kt + 1) * BC * HDIM;
            float* kd = sm + (size_t)nb * KVST;
            float* vd = sm + (size_t)(2 + nb) * KVST;
            for (int i = tid; i < 2048; i += 256) {
                int r = i >> 5;
                int c = (i & 31) * 4;
                cp_async16(kd + r * KSTRIDE + c, kp + (size_t)r * HDIM + c);
                cp_async16(vd + r * KSTRIDE + c, vp + (size_t)r * HDIM + c);
            }
            cp_async_commit();
            asm volatile("cp.async.wait_group 1;\n" ::: "memory");
        } else {
            asm volatile("cp.async.wait_group 0;\n" ::: "memory");
        }
        __syncthreads();

        const float* Ksc = sm + (size_t)cur * KVST;
        const float* Vsc = sm + (size_t)(2 + cur) * KVST;

        // ---- S = Q K^T (16x64 per warp) ----
        float sc[8][4];
        #pragma unroll
        for (int nt = 0; nt < 8; nt++)
            #pragma unroll
            for (int j = 0; j < 4; j++) sc[nt][j] = 0.0f;

        #pragma unroll
        for (int ks = 0; ks < 16; ks++) {
            int kb = ks * 8 + (lane & 3);
            #pragma unroll
            for (int nt = 0; nt < 8; nt++) {
                int n = nt * 8 + (lane >> 2);
                uint32_t bfr[2];
                bfr[0] = __float_as_uint(Ksc[n * KSTRIDE + kb]);
                bfr[1] = __float_as_uint(Ksc[n * KSTRIDE + kb + 4]);
                mma_tf32(sc[nt], qf[ks], bfr);
            }
        }

        // ---- causal mask (only tiles that can touch the diagonal) ----
        if (kt >= 2 * qi) {
            int grow0 = qi * BR + r0;
            #pragma unroll
            for (int nt = 0; nt < 8; nt++) {
                int cg = kt * BC + nt * 8 + (lane & 3) * 2;
                if (cg     > grow0)     sc[nt][0] = -1e30f;
                if (cg + 1 > grow0)     sc[nt][1] = -1e30f;
                if (cg     > grow0 + 8) sc[nt][2] = -1e30f;
                if (cg + 1 > grow0 + 8) sc[nt][3] = -1e30f;
            }
        }

        // ---- online softmax (base-2, scale folded into Q) ----
        float rx0 = -1e30f, rx1 = -1e30f;
        #pragma unroll
        for (int nt = 0; nt < 8; nt++) {
            rx0 = fmaxf(rx0, fmaxf(sc[nt][0], sc[nt][1]));
            rx1 = fmaxf(rx1, fmaxf(sc[nt][2], sc[nt][3]));
        }
        rx0 = fmaxf(rx0, __shfl_xor_sync(0xffffffffu, rx0, 1));
        rx0 = fmaxf(rx0, __shfl_xor_sync(0xffffffffu, rx0, 2));
        rx1 = fmaxf(rx1, __shfl_xor_sync(0xffffffffu, rx1, 1));
        rx1 = fmaxf(rx1, __shfl_xor_sync(0xffffffffu, rx1, 2));

        float mn0 = fmaxf(m0, rx0);
        float mn1 = fmaxf(m1, rx1);
        float al0 = exp2f(m0 - mn0);
        float al1 = exp2f(m1 - mn1);

        float s0 = 0.0f, s1 = 0.0f;
        #pragma unroll
        for (int nt = 0; nt < 8; nt++) {
            sc[nt][0] = exp2f(sc[nt][0] - mn0);
            sc[nt][1] = exp2f(sc[nt][1] - mn0);
            sc[nt][2] = exp2f(sc[nt][2] - mn1);
            sc[nt][3] = exp2f(sc[nt][3] - mn1);
            s0 += sc[nt][0] + sc[nt][1];
            s1 += sc[nt][2] + sc[nt][3];
        }
        s0 += __shfl_xor_sync(0xffffffffu, s0, 1);
        s0 += __shfl_xor_sync(0xffffffffu, s0, 2);
        s1 += __shfl_xor_sync(0xffffffffu, s1, 1);
        s1 += __shfl_xor_sync(0xffffffffu, s1, 2);

        l0 = l0 * al0 + s0;
        l1 = l1 * al1 + s1;
        m0 = mn0;
        m1 = mn1;

        #pragma unroll
        for (int nt = 0; nt < 16; nt++) {
            acc[nt][0] *= al0; acc[nt][1] *= al0;
            acc[nt][2] *= al1; acc[nt][3] *= al1;
        }

        // ---- P to smem (own rows only) ----
        #pragma unroll
        for (int nt = 0; nt < 8; nt++) {
            int c = nt * 8 + (lane & 3) * 2;
            Ps[r0 * PSTRIDE + c]           = tf32r(sc[nt][0]);
            Ps[r0 * PSTRIDE + c + 1]       = tf32r(sc[nt][1]);
            Ps[(r0 + 8) * PSTRIDE + c]     = tf32r(sc[nt][2]);
            Ps[(r0 + 8) * PSTRIDE + c + 1] = tf32r(sc[nt][3]);
        }
        __syncwarp();

        // ---- O += P @ V ----
        #pragma unroll
        for (int ks = 0; ks < 8; ks++) {
            int kb = ks * 8 + (lane & 3);
            uint32_t a[4];
            a[0] = __float_as_uint(Ps[r0 * PSTRIDE + kb]);
            a[1] = __float_as_uint(Ps[(r0 + 8) * PSTRIDE + kb]);
            a[2] = __float_as_uint(Ps[r0 * PSTRIDE + kb + 4]);
            a[3] = __float_as_uint(Ps[(r0 + 8) * PSTRIDE + kb + 4]);
            #pragma unroll
            for (int nt = 0; nt < 16; nt++) {
                int c = nt * 8 + (lane >> 2);
                uint32_t bfr[2];
                bfr[0] = __float_as_uint(Vsc[kb * KSTRIDE + c]);
                bfr[1] = __float_as_uint(Vsc[(kb + 4) * KSTRIDE + c]);
                mma_tf32(acc[nt], a, bfr);
            }
        }
        __syncthreads();
    }

    // epilogue: normalize, tf32-round (dense GEMM input), write [B,S,HID]
    float inv0 = 1.0f / l0;
    float inv1 = 1.0f / l1;
    int b = bh >> 4;
    int h = bh & 15;
    size_t rowg = (size_t)b * SEQ + (size_t)qi * BR + r0;
    float* out0 = g_attn + rowg * HID + (size_t)h * HDIM;
    float* out1 = out0 + (size_t)8 * HID;
    #pragma unroll
    for (int nt = 0; nt < 16; nt++) {
        int c = nt * 8 + (lane & 3) * 2;
        out0[c]     = tf32r(acc[nt][0] * inv0);
        out0[c + 1] = tf32r(acc[nt][1] * inv0);
        out1[c]     = tf32r(acc[nt][2] * inv1);
        out1[c + 1] = tf32r(acc[nt][3] * inv1);
    }
}

// ---------------------------------------------------------------------------
// Host launcher
// ---------------------------------------------------------------------------
extern "C" void kernel_launch(void* const* d_in, const int* in_sizes, int n_in,
                              void* d_out, int out_size)
{
    const float* hs      = (const float*)d_in[0];
    const float* w_qkv   = (const float*)d_in[1];
    const float* b_qkv   = (const float*)d_in[2];
    const float* w_dense = (const float*)d_in[3];
    const float* b_dense = (const float*)d_in[4];
    float* out = (float*)d_out;

    float *p_qkv, *p_attn, *p_hst, *p_wqkvt, *p_wdt;
    cudaGetSymbolAddress((void**)&p_qkv, g_qkv);
    cudaGetSymbolAddress((void**)&p_attn, g_attn);
    cudaGetSymbolAddress((void**)&p_hst, g_hst);
    cudaGetSymbolAddress((void**)&p_wqkvt, g_wqkvt);
    cudaGetSymbolAddress((void**)&p_wdt, g_wdt);

    const int gemm_smem = 2 * 2 * 128 * GSTRIDE * (int)sizeof(float);            // 73728
    const int attn_smem = (4 * KVST + BR * PSTRIDE) * (int)sizeof(float);        // 169984
    cudaFuncSetAttribute(gemm_tf32_kernel, cudaFuncAttributeMaxDynamicSharedMemorySize, gemm_smem);
    cudaFuncSetAttribute(attn_kernel, cudaFuncAttributeMaxDynamicSharedMemorySize, attn_smem);

    // 0) trig tables + tf32 pre-rounding of GEMM inputs
    trig_init_kernel<<<(SEQ * 64 + 255) / 256, 256>>>();
    cvt_tf32_kernel<<<(MROWS * HID / 4 + 255) / 256, 256>>>(hs, p_hst, MROWS * HID / 4);
    cvt_tf32_kernel<<<(NQKV * HID / 4 + 255) / 256, 256>>>(w_qkv, p_wqkvt, NQKV * HID / 4);
    cvt_tf32_kernel<<<(HID * HID / 4 + 255) / 256, 256>>>(w_dense, p_wdt, HID * HID / 4);

    // 1) QKV GEMM: [4096,2048] x [6144,2048]^T -> [4096,6144]
    gemm_tf32_kernel<<<dim3(NQKV / 128, MROWS / 128), 256, gemm_smem>>>(
        p_hst, p_wqkvt, b_qkv, p_qkv, MROWS, NQKV, HID);

    // 2) RoPE + scatter (writes tf32-rounded Q/K/V, Q pre-scaled)
    rope_scatter_kernel<<<(MROWS * HEADS * 64) / 256, 256>>>();

    // 3) causal flash attention
    attn_kernel<<<dim3(SEQ / BR, BH), 256, attn_smem>>>();

    // 4) dense GEMM: [4096,2048] x [2048,2048]^T -> [4096,2048]
    gemm_tf32_kernel<<<dim3(HID / 128, MROWS / 128), 256, gemm_smem>>>(
        p_attn, p_wdt, b_dense, out, MROWS, HID, HID);
}

// round 4
// speedup vs baseline: 1.3542x; 1.1183x over previous
#include <cuda_runtime.h>
#include <cuda_fp16.h>
#include <cstdint>
#include <math.h>

// Problem constants
#define BATCH   2
#define SEQ     2048
#define HEADS   16
#define HDIM    128
#define HID     2048
#define NQKV    6144
#define BH      (BATCH * HEADS)      // 32
#define MROWS   (BATCH * SEQ)        // 4096

// scale * log2(e) folded into Q:  (1/sqrt(128)) * 1.4426950408889634
#define QSCALE  0.12751742f

// ---------------------------------------------------------------------------
// Scratch (static device globals; no allocation allowed)
// ---------------------------------------------------------------------------
__device__ float  g_qkv [(size_t)MROWS * NQKV];          // 96 MB (f32 QKV out)
__device__ __half g_q  [(size_t)BH * SEQ * HDIM];        // 16 MB (fp16, scaled)
__device__ __half g_k  [(size_t)BH * SEQ * HDIM];        // 16 MB
__device__ __half g_v  [(size_t)BH * SEQ * HDIM];        // 16 MB
__device__ __half g_attn[(size_t)MROWS * HID];           // 16 MB (fp16 attn out)
__device__ __half g_hsh [(size_t)MROWS * HID];           // 16 MB (fp16 hs)
__device__ __half g_wqkvh[(size_t)NQKV * HID];           // 24 MB (fp16 w_qkv)
__device__ __half g_wdh [(size_t)HID * HID];             //  8 MB (fp16 w_dense)
__device__ float  g_cos[SEQ * 64];
__device__ float  g_sin[SEQ * 64];

// ---------------------------------------------------------------------------
// PTX helpers
// ---------------------------------------------------------------------------
__device__ __forceinline__ void mma_f16(float c[4], const uint32_t a[4], const uint32_t b[2]) {
    asm volatile(
        "mma.sync.aligned.m16n8k16.row.col.f32.f16.f16.f32 "
        "{%0,%1,%2,%3}, {%4,%5,%6,%7}, {%8,%9}, {%0,%1,%2,%3};\n"
        : "+f"(c[0]), "+f"(c[1]), "+f"(c[2]), "+f"(c[3])
        : "r"(a[0]), "r"(a[1]), "r"(a[2]), "r"(a[3]), "r"(b[0]), "r"(b[1]));
}

__device__ __forceinline__ void ldsm_x4(uint32_t r[4], uint32_t addr) {
    asm volatile("ldmatrix.sync.aligned.m8n8.x4.shared.b16 {%0,%1,%2,%3}, [%4];\n"
                 : "=r"(r[0]), "=r"(r[1]), "=r"(r[2]), "=r"(r[3]) : "r"(addr));
}

__device__ __forceinline__ void cp_async16(void* smem_dst, const void* gmem_src) {
    unsigned sa = (unsigned)__cvta_generic_to_shared(smem_dst);
    asm volatile("cp.async.cg.shared.global [%0], [%1], 16;\n" :: "r"(sa), "l"(gmem_src) : "memory");
}
__device__ __forceinline__ void cp_async_commit() {
    asm volatile("cp.async.commit_group;\n" ::: "memory");
}

// ---------------------------------------------------------------------------
// Kernel: trig tables (fp64 for accuracy at large angles)
// ---------------------------------------------------------------------------
__global__ void trig_init_kernel() {
    int idx = blockIdx.x * blockDim.x + threadIdx.x;   // SEQ*64 total
    if (idx >= SEQ * 64) return;
    int s  = idx >> 6;
    int d2 = idx & 63;
    double inv = exp(-(double)d2 * (9.210340371976184 / 64.0));  // 10000^(-d2/64)
    double ang = (double)s * inv;
    double cs, sn;
    sincos(ang, &sn, &cs);
    g_cos[idx] = (float)cs;
    g_sin[idx] = (float)sn;
}

// ---------------------------------------------------------------------------
// Kernel: elementwise f32 -> fp16 convert (float2 -> half2)
// ---------------------------------------------------------------------------
__global__ __launch_bounds__(256) void cvt_f16_kernel(const float* __restrict__ src,
                                                      __half* __restrict__ dst, int n2) {
    int i = blockIdx.x * blockDim.x + threadIdx.x;
    if (i >= n2) return;
    float2 v = ((const float2*)src)[i];
    ((__half2*)dst)[i] = __floats2half2_rn(v.x, v.y);
}

// ---------------------------------------------------------------------------
// fp16 GEMM:  C[m,n](f32) = sum_k A[m,k]*B[n,k] + bias[n]
// A,B fp16 [.,K] row-major. Tile 128x128x32 (halves), 256 threads (8 warps,
// warp tile 32x64), 3-stage cp.async pipeline, ldmatrix fragments.
// smem rows padded to 40 halves (80B) -> conflict-free ldmatrix.
// ---------------------------------------------------------------------------
#define GKS  40                 // halves per smem row
#define GSTG (128 * GKS)        // halves per matrix per stage (5120)
#define GEMM_SMEM (3 * 2 * GSTG * 2)   // 61440 B

__global__ __launch_bounds__(256) void gemm_f16_kernel(
    const __half* __restrict__ A, const __half* __restrict__ B,
    const float* __restrict__ bias, float* __restrict__ C,
    int M, int N, int K)
{
    extern __shared__ __half hsm[];
    uint32_t sbase = (uint32_t)__cvta_generic_to_shared(hsm);

    int tid  = threadIdx.x;
    int warp = tid >> 5;
    int lane = tid & 31;
    int bm   = blockIdx.y;
    int bn   = blockIdx.x;
    int wm   = warp >> 1;      // 0..3  (32 rows each)
    int wn   = warp & 1;       // 0..1  (64 cols each)

    const __half* Ab = A + (size_t)bm * 128 * K;
    const __half* Bb = B + (size_t)bn * 128 * K;
    int KT = K / 32;

    auto load_stage = [&](int c, int s) {
        __half* as = hsm + (size_t)s * 2 * GSTG;
        __half* bs = as + GSTG;
        const __half* Ag = Ab + (size_t)c * 32;
        const __half* Bg = Bb + (size_t)c * 32;
        #pragma unroll
        for (int u = 0; u < 2; u++) {
            int t = tid + u * 256;          // 0..511
            int r = t >> 2, ch = (t & 3) * 8;
            cp_async16(as + r * GKS + ch, Ag + (size_t)r * K + ch);
            cp_async16(bs + r * GKS + ch, Bg + (size_t)r * K + ch);
        }
    };

    load_stage(0, 0); cp_async_commit();
    load_stage(1, 1); cp_async_commit();

    float acc[2][8][4];
    #pragma unroll
    for (int i = 0; i < 2; i++)
        #pragma unroll
        for (int j = 0; j < 8; j++)
            #pragma unroll
            for (int k = 0; k < 4; k++) acc[i][j][k] = 0.0f;

    // ldmatrix lane addressing (precomputed pieces)
    int a_row = (lane & 7) + ((lane >> 3) & 1) * 8;   // row-within-16
    int a_k8  = (lane >> 4) * 8;                      // k col group
    int b_row = (lane & 7) + (lane >> 4) * 8;         // n-within-16
    int b_k8  = ((lane >> 3) & 1) * 8;

    for (int kt = 0; kt < KT; kt++) {
        asm volatile("cp.async.wait_group 1;\n" ::: "memory");
        __syncthreads();
        if (kt + 2 < KT) load_stage(kt + 2, (kt + 2) % 3);
        cp_async_commit();

        int s = kt % 3;
        uint32_t sa = sbase + (uint32_t)(s * 2 * GSTG) * 2;
        uint32_t sb = sa + GSTG * 2;

        #pragma unroll
        for (int ks2 = 0; ks2 < 2; ks2++) {
            uint32_t af[2][4];
            #pragma unroll
            for (int mt = 0; mt < 2; mt++) {
                uint32_t addr = sa + (uint32_t)(((wm * 32 + mt * 16 + a_row) * GKS
                                  + ks2 * 16 + a_k8) * 2);
                ldsm_x4(af[mt], addr);
            }
            uint32_t bfr[8][2];
            #pragma unroll
            for (int n16 = 0; n16 < 4; n16++) {
                uint32_t r[4];
                uint32_t addr = sb + (uint32_t)(((wn * 64 + n16 * 16 + b_row) * GKS
                                  + ks2 * 16 + b_k8) * 2);
                ldsm_x4(r, addr);
                bfr[n16 * 2][0]     = r[0]; bfr[n16 * 2][1]     = r[1];
                bfr[n16 * 2 + 1][0] = r[2]; bfr[n16 * 2 + 1][1] = r[3];
            }
            #pragma unroll
            for (int mt = 0; mt < 2; mt++)
                #pragma unroll
                for (int nt = 0; nt < 8; nt++)
                    mma_f16(acc[mt][nt], af[mt], bfr[nt]);
        }
    }

    // epilogue
    #pragma unroll
    for (int mt = 0; mt < 2; mt++) {
        int row = bm * 128 + wm * 32 + mt * 16 + (lane >> 2);
        #pragma unroll
        for (int nt = 0; nt < 8; nt++) {
            int col = bn * 128 + wn * 64 + nt * 8 + (lane & 3) * 2;
            float b0 = bias[col], b1 = bias[col + 1];
            C[(size_t)row * N + col]           = acc[mt][nt][0] + b0;
            C[(size_t)row * N + col + 1]       = acc[mt][nt][1] + b1;
            C[(size_t)(row + 8) * N + col]     = acc[mt][nt][2] + b0;
            C[(size_t)(row + 8) * N + col + 1] = acc[mt][nt][3] + b1;
        }
    }
}

// ---------------------------------------------------------------------------
// Kernel: RoPE + scatter qkv(f32) -> g_q (fp16, scaled), g_k, g_v (fp16)
// ---------------------------------------------------------------------------
__global__ __launch_bounds__(256) void rope_scatter_kernel() {
    int idx = blockIdx.x * blockDim.x + threadIdx.x;   // MROWS*HEADS*64
    int d2 = idx & 63;
    int h  = (idx >> 6) & 15;
    int s  = (idx >> 10) & 2047;
    int b  = idx >> 21;

    size_t row = (size_t)b * SEQ + s;
    const float* base = g_qkv + row * NQKV + (size_t)h * HDIM;

    float cs = g_cos[s * 64 + d2];
    float sn = g_sin[s * 64 + d2];

    float q1 = base[d2],          q2 = base[d2 + 64];
    float k1 = base[HID + d2],    k2 = base[HID + d2 + 64];
    float v1 = base[2*HID + d2],  v2 = base[2*HID + d2 + 64];

    int bh = b * HEADS + h;
    size_t o = ((size_t)bh * SEQ + s) * HDIM;
    g_q[o + d2]      = __float2half_rn((q1 * cs - q2 * sn) * QSCALE);
    g_q[o + d2 + 64] = __float2half_rn((q2 * cs + q1 * sn) * QSCALE);
    g_k[o + d2]      = __float2half_rn(k1 * cs - k2 * sn);
    g_k[o + d2 + 64] = __float2half_rn(k2 * cs + k1 * sn);
    g_v[o + d2]      = __float2half_rn(v1);
    g_v[o + d2 + 64] = __float2half_rn(v2);
}

// ---------------------------------------------------------------------------
// Causal flash attention: Br=128, Bc=64, 8 warps, fp16 mma m16n8k16
// Q fragments in registers; K/V double-buffered via cp.async.
// grid = (16 qtiles [reversed], 32 bh), block = 256
// smem (halves): Ks[2][64][136], Vs[2][64][136], Ps[128][72] = 88064 B
// ---------------------------------------------------------------------------
#define BR 128
#define BC 64
#define KS_H 136
#define PS_H 72
#define KVST_H (64 * KS_H)
#define ATTN_SMEM ((4 * KVST_H + BR * PS_H) * 2)

__global__ __launch_bounds__(256, 1) void attn_kernel() {
    extern __shared__ __half smh[];
    __half* Ps = smh + 4 * KVST_H;

    int tid  = threadIdx.x;
    int warp = tid >> 5;
    int lane = tid & 31;
    int qi   = gridDim.x - 1 - blockIdx.x;   // big tiles first
    int bh   = blockIdx.y;

    const __half* Qg = g_q + ((size_t)bh * SEQ + (size_t)qi * BR) * HDIM;
    const __half* Kg = g_k + (size_t)bh * SEQ * HDIM;
    const __half* Vg = g_v + (size_t)bh * SEQ * HDIM;

    int r0 = warp * 16 + (lane >> 2);      // local row (c0/c1); c2/c3 -> r0+8
    int kq = (lane & 3) * 2;               // k-pair offset within fragment

    // ---- Q fragments to registers (once): 8 ksteps of k16 ----
    uint32_t qf[8][4];
    #pragma unroll
    for (int ks = 0; ks < 8; ks++) {
        int kb = ks * 16 + kq;
        qf[ks][0] = __ldg((const uint32_t*)(Qg + (size_t)r0 * HDIM + kb));
        qf[ks][1] = __ldg((const uint32_t*)(Qg + (size_t)(r0 + 8) * HDIM + kb));
        qf[ks][2] = __ldg((const uint32_t*)(Qg + (size_t)r0 * HDIM + kb + 8));
        qf[ks][3] = __ldg((const uint32_t*)(Qg + (size_t)(r0 + 8) * HDIM + kb + 8));
    }

    int ktmax = 2 * qi + 1;

    // prologue: tile 0 -> buffer 0
    {
        __half* kd = smh;
        __half* vd = smh + 2 * KVST_H;
        for (int i = tid; i < 1024; i += 256) {
            int r = i >> 4;
            int c = (i & 15) * 8;
            cp_async16(kd + r * KS_H + c, Kg + (size_t)r * HDIM + c);
            cp_async16(vd + r * KS_H + c, Vg + (size_t)r * HDIM + c);
        }
        cp_async_commit();
    }

    float m0 = -1e30f, m1 = -1e30f;
    float l0 = 0.0f,   l1 = 0.0f;
    float acc[16][4];
    #pragma unroll
    for (int i = 0; i < 16; i++)
        #pragma unroll
        for (int j = 0; j < 4; j++) acc[i][j] = 0.0f;

    for (int kt = 0; kt <= ktmax; kt++) {
        int cur = kt & 1;
        if (kt < ktmax) {
            int nb = cur ^ 1;
            const __half* kp = Kg + (size_t)(kt + 1) * BC * HDIM;
            const __half* vp = Vg + (size_t)(kt + 1) * BC * HDIM;
            __half* kd = smh + (size_t)nb * KVST_H;
            __half* vd = smh + (size_t)(2 + nb) * KVST_H;
            for (int i = tid; i < 1024; i += 256) {
                int r = i >> 4;
                int c = (i & 15) * 8;
                cp_async16(kd + r * KS_H + c, kp + (size_t)r * HDIM + c);
                cp_async16(vd + r * KS_H + c, vp + (size_t)r * HDIM + c);
            }
            cp_async_commit();
            asm volatile("cp.async.wait_group 1;\n" ::: "memory");
        } else {
            asm volatile("cp.async.wait_group 0;\n" ::: "memory");
        }
        __syncthreads();

        const __half* Ksc = smh + (size_t)cur * KVST_H;
        const __half* Vsc = smh + (size_t)(2 + cur) * KVST_H;

        // ---- S = Q K^T (16x64 per warp), 8 ksteps x 8 ntiles ----
        float sc[8][4];
        #pragma unroll
        for (int nt = 0; nt < 8; nt++)
            #pragma unroll
            for (int j = 0; j < 4; j++) sc[nt][j] = 0.0f;

        #pragma unroll
        for (int ks = 0; ks < 8; ks++) {
            int kb = ks * 16 + kq;
            #pragma unroll
            for (int nt = 0; nt < 8; nt++) {
                int n = nt * 8 + (lane >> 2);
                uint32_t bfr[2];
                bfr[0] = *(const uint32_t*)(Ksc + n * KS_H + kb);
                bfr[1] = *(const uint32_t*)(Ksc + n * KS_H + kb + 8);
                mma_f16(sc[nt], qf[ks], bfr);
            }
        }

        // ---- causal mask (only tiles touching the diagonal) ----
        if (kt >= 2 * qi) {
            int grow0 = qi * BR + r0;
            #pragma unroll
            for (int nt = 0; nt < 8; nt++) {
                int cg = kt * BC + nt * 8 + (lane & 3) * 2;
                if (cg     > grow0)     sc[nt][0] = -1e30f;
                if (cg + 1 > grow0)     sc[nt][1] = -1e30f;
                if (cg     > grow0 + 8) sc[nt][2] = -1e30f;
                if (cg + 1 > grow0 + 8) sc[nt][3] = -1e30f;
            }
        }

        // ---- online softmax (base-2, scale folded into Q) ----
        float rx0 = -1e30f, rx1 = -1e30f;
        #pragma unroll
        for (int nt = 0; nt < 8; nt++) {
            rx0 = fmaxf(rx0, fmaxf(sc[nt][0], sc[nt][1]));
            rx1 = fmaxf(rx1, fmaxf(sc[nt][2], sc[nt][3]));
        }
        rx0 = fmaxf(rx0, __shfl_xor_sync(0xffffffffu, rx0, 1));
        rx0 = fmaxf(rx0, __shfl_xor_sync(0xffffffffu, rx0, 2));
        rx1 = fmaxf(rx1, __shfl_xor_sync(0xffffffffu, rx1, 1));
        rx1 = fmaxf(rx1, __shfl_xor_sync(0xffffffffu, rx1, 2));

        float mn0 = fmaxf(m0, rx0);
        float mn1 = fmaxf(m1, rx1);
        float al0 = exp2f(m0 - mn0);
        float al1 = exp2f(m1 - mn1);

        float s0 = 0.0f, s1 = 0.0f;
        #pragma unroll
        for (int nt = 0; nt < 8; nt++) {
            sc[nt][0] = exp2f(sc[nt][0] - mn0);
            sc[nt][1] = exp2f(sc[nt][1] - mn0);
            sc[nt][2] = exp2f(sc[nt][2] - mn1);
            sc[nt][3] = exp2f(sc[nt][3] - mn1);
            s0 += sc[nt][0] + sc[nt][1];
            s1 += sc[nt][2] + sc[nt][3];
        }
        s0 += __shfl_xor_sync(0xffffffffu, s0, 1);
        s0 += __shfl_xor_sync(0xffffffffu, s0, 2);
        s1 += __shfl_xor_sync(0xffffffffu, s1, 1);
        s1 += __shfl_xor_sync(0xffffffffu, s1, 2);

        l0 = l0 * al0 + s0;
        l1 = l1 * al1 + s1;
        m0 = mn0;
        m1 = mn1;

        #pragma unroll
        for (int nt = 0; nt < 16; nt++) {
            acc[nt][0] *= al0; acc[nt][1] *= al0;
            acc[nt][2] *= al1; acc[nt][3] *= al1;
        }

        // ---- P to smem as fp16 (own rows only) ----
        #pragma unroll
        for (int nt = 0; nt < 8; nt++) {
            int c = nt * 8 + (lane & 3) * 2;
            *(__half2*)(Ps + r0 * PS_H + c)       = __floats2half2_rn(sc[nt][0], sc[nt][1]);
            *(__half2*)(Ps + (r0 + 8) * PS_H + c) = __floats2half2_rn(sc[nt][2], sc[nt][3]);
        }
        __syncwarp();

        // ---- O += P @ V : 4 ksteps (k64) x 16 ntiles (n128) ----
        #pragma unroll
        for (int ks = 0; ks < 4; ks++) {
            int kb = ks * 16 + kq;
            uint32_t a[4];
            a[0] = *(const uint32_t*)(Ps + r0 * PS_H + kb);
            a[1] = *(const uint32_t*)(Ps + (r0 + 8) * PS_H + kb);
            a[2] = *(const uint32_t*)(Ps + r0 * PS_H + kb + 8);
            a[3] = *(const uint32_t*)(Ps + (r0 + 8) * PS_H + kb + 8);
            #pragma unroll
            for (int nt = 0; nt < 16; nt++) {
                int n = nt * 8 + (lane >> 2);
                uint32_t bfr[2];
                __half2 v0 = __halves2half2(Vsc[(kb)     * KS_H + n], Vsc[(kb + 1) * KS_H + n]);
                __half2 v1 = __halves2half2(Vsc[(kb + 8) * KS_H + n], Vsc[(kb + 9) * KS_H + n]);
                bfr[0] = *(uint32_t*)&v0;
                bfr[1] = *(uint32_t*)&v1;
                mma_f16(acc[nt], a, bfr);
            }
        }
        __syncthreads();
    }

    // epilogue: normalize, convert fp16 (dense GEMM input), write [B,S,HID]
    float inv0 = 1.0f / l0;
    float inv1 = 1.0f / l1;
    int b = bh >> 4;
    int h = bh & 15;
    size_t rowg = (size_t)b * SEQ + (size_t)qi * BR + r0;
    __half* out0 = g_attn + rowg * HID + (size_t)h * HDIM;
    __half* out1 = out0 + (size_t)8 * HID;
    #pragma unroll
    for (int nt = 0; nt < 16; nt++) {
        int c = nt * 8 + (lane & 3) * 2;
        *(__half2*)(out0 + c) = __floats2half2_rn(acc[nt][0] * inv0, acc[nt][1] * inv0);
        *(__half2*)(out1 + c) = __floats2half2_rn(acc[nt][2] * inv1, acc[nt][3] * inv1);
    }
}

// ---------------------------------------------------------------------------
// Host launcher
// ---------------------------------------------------------------------------
extern "C" void kernel_launch(void* const* d_in, const int* in_sizes, int n_in,
                              void* d_out, int out_size)
{
    const float* hs      = (const float*)d_in[0];
    const float* w_qkv   = (const float*)d_in[1];
    const float* b_qkv   = (const float*)d_in[2];
    const float* w_dense = (const float*)d_in[3];
    const float* b_dense = (const float*)d_in[4];
    float* out = (float*)d_out;

    float  *p_qkv;
    __half *p_attn, *p_hsh, *p_wqkvh, *p_wdh;
    cudaGetSymbolAddress((void**)&p_qkv,   g_qkv);
    cudaGetSymbolAddress((void**)&p_attn,  g_attn);
    cudaGetSymbolAddress((void**)&p_hsh,   g_hsh);
    cudaGetSymbolAddress((void**)&p_wqkvh, g_wqkvh);
    cudaGetSymbolAddress((void**)&p_wdh,   g_wdh);

    cudaFuncSetAttribute(gemm_f16_kernel, cudaFuncAttributeMaxDynamicSharedMemorySize, GEMM_SMEM);
    cudaFuncSetAttribute(attn_kernel,     cudaFuncAttributeMaxDynamicSharedMemorySize, ATTN_SMEM);

    // 0) trig tables + fp16 conversion of GEMM inputs
    trig_init_kernel<<<(SEQ * 64 + 255) / 256, 256>>>();
    cvt_f16_kernel<<<(MROWS * HID / 2 + 255) / 256, 256>>>(hs, p_hsh, MROWS * HID / 2);
    cvt_f16_kernel<<<(NQKV * HID / 2 + 255) / 256, 256>>>(w_qkv, p_wqkvh, NQKV * HID / 2);
    cvt_f16_kernel<<<(HID * HID / 2 + 255) / 256, 256>>>(w_dense, p_wdh, HID * HID / 2);

    // 1) QKV GEMM (fp16 in, f32 out): [4096,2048] x [6144,2048]^T -> [4096,6144]
    gemm_f16_kernel<<<dim3(NQKV / 128, MROWS / 128), 256, GEMM_SMEM>>>(
        p_hsh, p_wqkvh, b_qkv, p_qkv, MROWS, NQKV, HID);

    // 2) RoPE + scatter (fp16 Q/K/V, Q pre-scaled)
    rope_scatter_kernel<<<(MROWS * HEADS * 64) / 256, 256>>>();

    // 3) causal flash attention (fp16 mma, fp16 output)
    attn_kernel<<<dim3(SEQ / BR, BH), 256, ATTN_SMEM>>>();

    // 4) dense GEMM (fp16 in, f32 out): [4096,2048] x [2048,2048]^T -> [4096,2048]
    gemm_f16_kernel<<<dim3(HID / 128, MROWS / 128), 256, GEMM_SMEM>>>(
        p_attn, p_wdh, b_dense, out, MROWS, HID, HID);
}

// round 5
// speedup vs baseline: 2.1999x; 1.6245x over previous
#include <cuda_runtime.h>
#include <cuda_fp16.h>
#include <cstdint>
#include <math.h>

// Problem constants
#define BATCH   2
#define SEQ     2048
#define HEADS   16
#define HDIM    128
#define HID     2048
#define NQKV    6144
#define BH      (BATCH * HEADS)      // 32
#define MROWS   (BATCH * SEQ)        // 4096

// scale * log2(e) folded into Q:  (1/sqrt(128)) * 1.4426950408889634
#define QSCALE  0.12751742f

// ---------------------------------------------------------------------------
// Scratch (static device globals; no allocation allowed)
// ---------------------------------------------------------------------------
__device__ float  g_qkv [(size_t)MROWS * NQKV];          // 96 MB (f32 QKV out)
__device__ __half g_q  [(size_t)BH * SEQ * HDIM];        // 16 MB (fp16, scaled)
__device__ __half g_k  [(size_t)BH * SEQ * HDIM];        // 16 MB
__device__ __half g_v  [(size_t)BH * SEQ * HDIM];        // 16 MB
__device__ __half g_attn[(size_t)MROWS * HID];           // 16 MB (fp16 attn out)
__device__ __half g_hsh [(size_t)MROWS * HID];           // 16 MB (fp16 hs)
__device__ __half g_wqkvh[(size_t)NQKV * HID];           // 24 MB (fp16 w_qkv)
__device__ __half g_wdh [(size_t)HID * HID];             //  8 MB (fp16 w_dense)
__device__ float  g_cos[SEQ * 64];
__device__ float  g_sin[SEQ * 64];

// ---------------------------------------------------------------------------
// PTX helpers
// ---------------------------------------------------------------------------
__device__ __forceinline__ void mma_f16(float c[4], const uint32_t a[4], const uint32_t b[2]) {
    asm volatile(
        "mma.sync.aligned.m16n8k16.row.col.f32.f16.f16.f32 "
        "{%0,%1,%2,%3}, {%4,%5,%6,%7}, {%8,%9}, {%0,%1,%2,%3};\n"
        : "+f"(c[0]), "+f"(c[1]), "+f"(c[2]), "+f"(c[3])
        : "r"(a[0]), "r"(a[1]), "r"(a[2]), "r"(a[3]), "r"(b[0]), "r"(b[1]));
}

__device__ __forceinline__ void ldsm_x4(uint32_t r[4], uint32_t addr) {
    asm volatile("ldmatrix.sync.aligned.m8n8.x4.shared.b16 {%0,%1,%2,%3}, [%4];\n"
                 : "=r"(r[0]), "=r"(r[1]), "=r"(r[2]), "=r"(r[3]) : "r"(addr));
}
__device__ __forceinline__ void ldsm_x4_t(uint32_t r[4], uint32_t addr) {
    asm volatile("ldmatrix.sync.aligned.m8n8.x4.trans.shared.b16 {%0,%1,%2,%3}, [%4];\n"
                 : "=r"(r[0]), "=r"(r[1]), "=r"(r[2]), "=r"(r[3]) : "r"(addr));
}

__device__ __forceinline__ void cp_async16(void* smem_dst, const void* gmem_src) {
    unsigned sa = (unsigned)__cvta_generic_to_shared(smem_dst);
    asm volatile("cp.async.cg.shared.global [%0], [%1], 16;\n" :: "r"(sa), "l"(gmem_src) : "memory");
}
__device__ __forceinline__ void cp_async_commit() {
    asm volatile("cp.async.commit_group;\n" ::: "memory");
}
__device__ __forceinline__ uint32_t packh2(float x, float y) {
    __half2 h = __floats2half2_rn(x, y);
    return *(uint32_t*)&h;
}

// ---------------------------------------------------------------------------
// Kernel: trig tables (fp64 for accuracy at large angles)
// ---------------------------------------------------------------------------
__global__ void trig_init_kernel() {
    int idx = blockIdx.x * blockDim.x + threadIdx.x;   // SEQ*64 total
    if (idx >= SEQ * 64) return;
    int s  = idx >> 6;
    int d2 = idx & 63;
    double inv = exp(-(double)d2 * (9.210340371976184 / 64.0));  // 10000^(-d2/64)
    double ang = (double)s * inv;
    double cs, sn;
    sincos(ang, &sn, &cs);
    g_cos[idx] = (float)cs;
    g_sin[idx] = (float)sn;
}

// ---------------------------------------------------------------------------
// Kernel: elementwise f32 -> fp16 convert (float2 -> half2)
// ---------------------------------------------------------------------------
__global__ __launch_bounds__(256) void cvt_f16_kernel(const float* __restrict__ src,
                                                      __half* __restrict__ dst, int n2) {
    int i = blockIdx.x * blockDim.x + threadIdx.x;
    if (i >= n2) return;
    float2 v = ((const float2*)src)[i];
    ((__half2*)dst)[i] = __floats2half2_rn(v.x, v.y);
}

// ---------------------------------------------------------------------------
// fp16 GEMM:  C[m,n](f32) = sum_k A[m,k]*B[n,k] + bias[n]
// Tile 128x128x32 (halves), 256 threads (8 warps, warp tile 32x64),
// 3-stage cp.async pipeline, ldmatrix fragments. 80B padded rows.
// ---------------------------------------------------------------------------
#define GKS  40                 // halves per smem row
#define GSTG (128 * GKS)        // halves per matrix per stage (5120)
#define GEMM_SMEM (3 * 2 * GSTG * 2)   // 61440 B

__global__ __launch_bounds__(256) void gemm_f16_kernel(
    const __half* __restrict__ A, const __half* __restrict__ B,
    const float* __restrict__ bias, float* __restrict__ C,
    int M, int N, int K)
{
    extern __shared__ __half hsm[];
    uint32_t sbase = (uint32_t)__cvta_generic_to_shared(hsm);

    int tid  = threadIdx.x;
    int warp = tid >> 5;
    int lane = tid & 31;
    int bm   = blockIdx.y;
    int bn   = blockIdx.x;
    int wm   = warp >> 1;      // 0..3  (32 rows each)
    int wn   = warp & 1;       // 0..1  (64 cols each)

    const __half* Ab = A + (size_t)bm * 128 * K;
    const __half* Bb = B + (size_t)bn * 128 * K;
    int KT = K / 32;

    auto load_stage = [&](int c, int s) {
        __half* as = hsm + (size_t)s * 2 * GSTG;
        __half* bs = as + GSTG;
        const __half* Ag = Ab + (size_t)c * 32;
        const __half* Bg = Bb + (size_t)c * 32;
        #pragma unroll
        for (int u = 0; u < 2; u++) {
            int t = tid + u * 256;          // 0..511
            int r = t >> 2, ch = (t & 3) * 8;
            cp_async16(as + r * GKS + ch, Ag + (size_t)r * K + ch);
            cp_async16(bs + r * GKS + ch, Bg + (size_t)r * K + ch);
        }
    };

    load_stage(0, 0); cp_async_commit();
    load_stage(1, 1); cp_async_commit();

    float acc[2][8][4];
    #pragma unroll
    for (int i = 0; i < 2; i++)
        #pragma unroll
        for (int j = 0; j < 8; j++)
            #pragma unroll
            for (int k = 0; k < 4; k++) acc[i][j][k] = 0.0f;

    int a_row = (lane & 7) + ((lane >> 3) & 1) * 8;
    int a_k8  = (lane >> 4) * 8;
    int b_row = (lane & 7) + (lane >> 4) * 8;
    int b_k8  = ((lane >> 3) & 1) * 8;

    for (int kt = 0; kt < KT; kt++) {
        asm volatile("cp.async.wait_group 1;\n" ::: "memory");
        __syncthreads();
        if (kt + 2 < KT) load_stage(kt + 2, (kt + 2) % 3);
        cp_async_commit();

        int s = kt % 3;
        uint32_t sa = sbase + (uint32_t)(s * 2 * GSTG) * 2;
        uint32_t sb = sa + GSTG * 2;

        #pragma unroll
        for (int ks2 = 0; ks2 < 2; ks2++) {
            uint32_t af[2][4];
            #pragma unroll
            for (int mt = 0; mt < 2; mt++) {
                uint32_t addr = sa + (uint32_t)(((wm * 32 + mt * 16 + a_row) * GKS
                                  + ks2 * 16 + a_k8) * 2);
                ldsm_x4(af[mt], addr);
            }
            uint32_t bfr[8][2];
            #pragma unroll
            for (int n16 = 0; n16 < 4; n16++) {
                uint32_t r[4];
                uint32_t addr = sb + (uint32_t)(((wn * 64 + n16 * 16 + b_row) * GKS
                                  + ks2 * 16 + b_k8) * 2);
                ldsm_x4(r, addr);
                bfr[n16 * 2][0]     = r[0]; bfr[n16 * 2][1]     = r[1];
                bfr[n16 * 2 + 1][0] = r[2]; bfr[n16 * 2 + 1][1] = r[3];
            }
            #pragma unroll
            for (int mt = 0; mt < 2; mt++)
                #pragma unroll
                for (int nt = 0; nt < 8; nt++)
                    mma_f16(acc[mt][nt], af[mt], bfr[nt]);
        }
    }

    #pragma unroll
    for (int mt = 0; mt < 2; mt++) {
        int row = bm * 128 + wm * 32 + mt * 16 + (lane >> 2);
        #pragma unroll
        for (int nt = 0; nt < 8; nt++) {
            int col = bn * 128 + wn * 64 + nt * 8 + (lane & 3) * 2;
            float b0 = bias[col], b1 = bias[col + 1];
            C[(size_t)row * N + col]           = acc[mt][nt][0] + b0;
            C[(size_t)row * N + col + 1]       = acc[mt][nt][1] + b1;
            C[(size_t)(row + 8) * N + col]     = acc[mt][nt][2] + b0;
            C[(size_t)(row + 8) * N + col + 1] = acc[mt][nt][3] + b1;
        }
    }
}

// ---------------------------------------------------------------------------
// Kernel: RoPE + scatter qkv(f32) -> g_q (fp16, scaled), g_k, g_v (fp16)
// ---------------------------------------------------------------------------
__global__ __launch_bounds__(256) void rope_scatter_kernel() {
    int idx = blockIdx.x * blockDim.x + threadIdx.x;   // MROWS*HEADS*64
    int d2 = idx & 63;
    int h  = (idx >> 6) & 15;
    int s  = (idx >> 10) & 2047;
    int b  = idx >> 21;

    size_t row = (size_t)b * SEQ + s;
    const float* base = g_qkv + row * NQKV + (size_t)h * HDIM;

    float cs = g_cos[s * 64 + d2];
    float sn = g_sin[s * 64 + d2];

    float q1 = base[d2],          q2 = base[d2 + 64];
    float k1 = base[HID + d2],    k2 = base[HID + d2 + 64];
    float v1 = base[2*HID + d2],  v2 = base[2*HID + d2 + 64];

    int bh = b * HEADS + h;
    size_t o = ((size_t)bh * SEQ + s) * HDIM;
    g_q[o + d2]      = __float2half_rn((q1 * cs - q2 * sn) * QSCALE);
    g_q[o + d2 + 64] = __float2half_rn((q2 * cs + q1 * sn) * QSCALE);
    g_k[o + d2]      = __float2half_rn(k1 * cs - k2 * sn);
    g_k[o + d2 + 64] = __float2half_rn(k2 * cs + k1 * sn);
    g_v[o + d2]      = __float2half_rn(v1);
    g_v[o + d2 + 64] = __float2half_rn(v2);
}

// ---------------------------------------------------------------------------
// Causal flash attention: Br=128, Bc=64, 8 warps, fp16 mma m16n8k16
// Q fragments + P registers resident; K via ldmatrix, V via ldmatrix.trans.
// grid = (16 qtiles [reversed], 32 bh), block = 256
// smem (halves): Ks[2][64][136], Vs[2][64][136] = 69632 B
// ---------------------------------------------------------------------------
#define BR 128
#define BC 64
#define KS_H 136
#define KVST_H (64 * KS_H)
#define ATTN_SMEM (4 * KVST_H * 2)

__global__ __launch_bounds__(256, 1) void attn_kernel() {
    extern __shared__ __half smh[];
    uint32_t sb_attn = (uint32_t)__cvta_generic_to_shared(smh);

    int tid  = threadIdx.x;
    int warp = tid >> 5;
    int lane = tid & 31;
    int qi   = gridDim.x - 1 - blockIdx.x;   // big tiles first
    int bh   = blockIdx.y;

    const __half* Qg = g_q + ((size_t)bh * SEQ + (size_t)qi * BR) * HDIM;
    const __half* Kg = g_k + (size_t)bh * SEQ * HDIM;
    const __half* Vg = g_v + (size_t)bh * SEQ * HDIM;

    int r0 = warp * 16 + (lane >> 2);      // local row (c0/c1); c2/c3 -> r0+8
    int kq = (lane & 3) * 2;               // k-pair offset within fragment

    // ldmatrix lane addressing
    int b_row = (lane & 7) + (lane >> 4) * 8;        // non-trans (K)
    int b_k8  = ((lane >> 3) & 1) * 8;
    int v_mi  = lane >> 3;                           // trans (V): matrix idx
    int v_r   = lane & 7;
    int v_rowoff = (v_mi & 1) * 8 + v_r;             // k-row within 16
    int v_coloff = (v_mi >> 1) * 8;                  // n-col within 16

    // ---- Q fragments to registers (once): 8 ksteps of k16 ----
    uint32_t qf[8][4];
    #pragma unroll
    for (int ks = 0; ks < 8; ks++) {
        int kb = ks * 16 + kq;
        qf[ks][0] = __ldg((const uint32_t*)(Qg + (size_t)r0 * HDIM + kb));
        qf[ks][1] = __ldg((const uint32_t*)(Qg + (size_t)(r0 + 8) * HDIM + kb));
        qf[ks][2] = __ldg((const uint32_t*)(Qg + (size_t)r0 * HDIM + kb + 8));
        qf[ks][3] = __ldg((const uint32_t*)(Qg + (size_t)(r0 + 8) * HDIM + kb + 8));
    }

    int ktmax = 2 * qi + 1;

    // prologue: tile 0 -> buffer 0
    {
        __half* kd = smh;
        __half* vd = smh + 2 * KVST_H;
        for (int i = tid; i < 1024; i += 256) {
            int r = i >> 4;
            int c = (i & 15) * 8;
            cp_async16(kd + r * KS_H + c, Kg + (size_t)r * HDIM + c);
            cp_async16(vd + r * KS_H + c, Vg + (size_t)r * HDIM + c);
        }
        cp_async_commit();
    }

    float m0 = -1e30f, m1 = -1e30f;
    float l0 = 0.0f,   l1 = 0.0f;
    float acc[16][4];
    #pragma unroll
    for (int i = 0; i < 16; i++)
        #pragma unroll
        for (int j = 0; j < 4; j++) acc[i][j] = 0.0f;

    for (int kt = 0; kt <= ktmax; kt++) {
        int cur = kt & 1;
        if (kt < ktmax) {
            int nb = cur ^ 1;
            const __half* kp = Kg + (size_t)(kt + 1) * BC * HDIM;
            const __half* vp = Vg + (size_t)(kt + 1) * BC * HDIM;
            __half* kd = smh + (size_t)nb * KVST_H;
            __half* vd = smh + (size_t)(2 + nb) * KVST_H;
            for (int i = tid; i < 1024; i += 256) {
                int r = i >> 4;
                int c = (i & 15) * 8;
                cp_async16(kd + r * KS_H + c, kp + (size_t)r * HDIM + c);
                cp_async16(vd + r * KS_H + c, vp + (size_t)r * HDIM + c);
            }
            cp_async_commit();
            asm volatile("cp.async.wait_group 1;\n" ::: "memory");
        } else {
            asm volatile("cp.async.wait_group 0;\n" ::: "memory");
        }
        __syncthreads();

        uint32_t kbase = sb_attn + (uint32_t)(cur * KVST_H) * 2;
        uint32_t vbase = sb_attn + (uint32_t)((2 + cur) * KVST_H) * 2;

        // ---- S = Q K^T (16x64 per warp): K via ldmatrix.x4 ----
        float sc[8][4];
        #pragma unroll
        for (int nt = 0; nt < 8; nt++)
            #pragma unroll
            for (int j = 0; j < 4; j++) sc[nt][j] = 0.0f;

        #pragma unroll
        for (int ks = 0; ks < 8; ks++) {
            #pragma unroll
            for (int n16 = 0; n16 < 4; n16++) {
                uint32_t r[4];
                uint32_t addr = kbase + (uint32_t)(((n16 * 16 + b_row) * KS_H
                                  + ks * 16 + b_k8) * 2);
                ldsm_x4(r, addr);
                uint32_t bf0[2] = {r[0], r[1]};
                uint32_t bf1[2] = {r[2], r[3]};
                mma_f16(sc[n16 * 2],     qf[ks], bf0);
                mma_f16(sc[n16 * 2 + 1], qf[ks], bf1);
            }
        }

        // ---- causal mask (only tiles touching the diagonal) ----
        if (kt >= 2 * qi) {
            int grow0 = qi * BR + r0;
            #pragma unroll
            for (int nt = 0; nt < 8; nt++) {
                int cg = kt * BC + nt * 8 + (lane & 3) * 2;
                if (cg     > grow0)     sc[nt][0] = -1e30f;
                if (cg + 1 > grow0)     sc[nt][1] = -1e30f;
                if (cg     > grow0 + 8) sc[nt][2] = -1e30f;
                if (cg + 1 > grow0 + 8) sc[nt][3] = -1e30f;
            }
        }

        // ---- online softmax (base-2, scale folded into Q) ----
        float rx0 = -1e30f, rx1 = -1e30f;
        #pragma unroll
        for (int nt = 0; nt < 8; nt++) {
            rx0 = fmaxf(rx0, fmaxf(sc[nt][0], sc[nt][1]));
            rx1 = fmaxf(rx1, fmaxf(sc[nt][2], sc[nt][3]));
        }
        rx0 = fmaxf(rx0, __shfl_xor_sync(0xffffffffu, rx0, 1));
        rx0 = fmaxf(rx0, __shfl_xor_sync(0xffffffffu, rx0, 2));
        rx1 = fmaxf(rx1, __shfl_xor_sync(0xffffffffu, rx1, 1));
        rx1 = fmaxf(rx1, __shfl_xor_sync(0xffffffffu, rx1, 2));

        float mn0 = fmaxf(m0, rx0);
        float mn1 = fmaxf(m1, rx1);
        float al0 = exp2f(m0 - mn0);
        float al1 = exp2f(m1 - mn1);

        float s0 = 0.0f, s1 = 0.0f;
        #pragma unroll
        for (int nt = 0; nt < 8; nt++) {
            sc[nt][0] = exp2f(sc[nt][0] - mn0);
            sc[nt][1] = exp2f(sc[nt][1] - mn0);
            sc[nt][2] = exp2f(sc[nt][2] - mn1);
            sc[nt][3] = exp2f(sc[nt][3] - mn1);
            s0 += sc[nt][0] + sc[nt][1];
            s1 += sc[nt][2] + sc[nt][3];
        }
        s0 += __shfl_xor_sync(0xffffffffu, s0, 1);
        s0 += __shfl_xor_sync(0xffffffffu, s0, 2);
        s1 += __shfl_xor_sync(0xffffffffu, s1, 1);
        s1 += __shfl_xor_sync(0xffffffffu, s1, 2);

        l0 = l0 * al0 + s0;
        l1 = l1 * al1 + s1;
        m0 = mn0;
        m1 = mn1;

        #pragma unroll
        for (int nt = 0; nt < 16; nt++) {
            acc[nt][0] *= al0; acc[nt][1] *= al0;
            acc[nt][2] *= al1; acc[nt][3] *= al1;
        }

        // ---- P -> A fragments in registers (no smem roundtrip) ----
        uint32_t pf[4][4];
        #pragma unroll
        for (int ks = 0; ks < 4; ks++) {
            pf[ks][0] = packh2(sc[2*ks][0],     sc[2*ks][1]);
            pf[ks][1] = packh2(sc[2*ks][2],     sc[2*ks][3]);
            pf[ks][2] = packh2(sc[2*ks + 1][0], sc[2*ks + 1][1]);
            pf[ks][3] = packh2(sc[2*ks + 1][2], sc[2*ks + 1][3]);
        }

        // ---- O += P @ V : V via ldmatrix.x4.trans ----
        #pragma unroll
        for (int ks = 0; ks < 4; ks++) {
            #pragma unroll
            for (int n16 = 0; n16 < 8; n16++) {
                uint32_t r[4];
                uint32_t addr = vbase + (uint32_t)(((ks * 16 + v_rowoff) * KS_H
                                  + n16 * 16 + v_coloff) * 2);
                ldsm_x4_t(r, addr);
                uint32_t bf0[2] = {r[0], r[1]};
                uint32_t bf1[2] = {r[2], r[3]};
                mma_f16(acc[n16 * 2],     pf[ks], bf0);
                mma_f16(acc[n16 * 2 + 1], pf[ks], bf1);
            }
        }
        __syncthreads();
    }

    // epilogue: normalize, convert fp16 (dense GEMM input), write [B,S,HID]
    float inv0 = 1.0f / l0;
    float inv1 = 1.0f / l1;
    int b = bh >> 4;
    int h = bh & 15;
    size_t rowg = (size_t)b * SEQ + (size_t)qi * BR + r0;
    __half* out0 = g_attn + rowg * HID + (size_t)h * HDIM;
    __half* out1 = out0 + (size_t)8 * HID;
    #pragma unroll
    for (int nt = 0; nt < 16; nt++) {
        int c = nt * 8 + (lane & 3) * 2;
        *(__half2*)(out0 + c) = __floats2half2_rn(acc[nt][0] * inv0, acc[nt][1] * inv0);
        *(__half2*)(out1 + c) = __floats2half2_rn(acc[nt][2] * inv1, acc[nt][3] * inv1);
    }
}

// ---------------------------------------------------------------------------
// Host launcher
// ---------------------------------------------------------------------------
extern "C" void kernel_launch(void* const* d_in, const int* in_sizes, int n_in,
                              void* d_out, int out_size)
{
    const float* hs      = (const float*)d_in[0];
    const float* w_qkv   = (const float*)d_in[1];
    const float* b_qkv   = (const float*)d_in[2];
    const float* w_dense = (const float*)d_in[3];
    const float* b_dense = (const float*)d_in[4];
    float* out = (float*)d_out;

    float  *p_qkv;
    __half *p_attn, *p_hsh, *p_wqkvh, *p_wdh;
    cudaGetSymbolAddress((void**)&p_qkv,   g_qkv);
    cudaGetSymbolAddress((void**)&p_attn,  g_attn);
    cudaGetSymbolAddress((void**)&p_hsh,   g_hsh);
    cudaGetSymbolAddress((void**)&p_wqkvh, g_wqkvh);
    cudaGetSymbolAddress((void**)&p_wdh,   g_wdh);

    cudaFuncSetAttribute(gemm_f16_kernel, cudaFuncAttributeMaxDynamicSharedMemorySize, GEMM_SMEM);
    cudaFuncSetAttribute(attn_kernel,     cudaFuncAttributeMaxDynamicSharedMemorySize, ATTN_SMEM);

    // 0) trig tables + fp16 conversion of GEMM inputs
    trig_init_kernel<<<(SEQ * 64 + 255) / 256, 256>>>();
    cvt_f16_kernel<<<(MROWS * HID / 2 + 255) / 256, 256>>>(hs, p_hsh, MROWS * HID / 2);
    cvt_f16_kernel<<<(NQKV * HID / 2 + 255) / 256, 256>>>(w_qkv, p_wqkvh, NQKV * HID / 2);
    cvt_f16_kernel<<<(HID * HID / 2 + 255) / 256, 256>>>(w_dense, p_wdh, HID * HID / 2);

    // 1) QKV GEMM (fp16 in, f32 out): [4096,2048] x [6144,2048]^T -> [4096,6144]
    gemm_f16_kernel<<<dim3(NQKV / 128, MROWS / 128), 256, GEMM_SMEM>>>(
        p_hsh, p_wqkvh, b_qkv, p_qkv, MROWS, NQKV, HID);

    // 2) RoPE + scatter (fp16 Q/K/V, Q pre-scaled)
    rope_scatter_kernel<<<(MROWS * HEADS * 64) / 256, 256>>>();

    // 3) causal flash attention (fp16 mma)
    attn_kernel<<<dim3(SEQ / BR, BH), 256, ATTN_SMEM>>>();

    // 4) dense GEMM (fp16 in, f32 out): [4096,2048] x [2048,2048]^T -> [4096,2048]
    gemm_f16_kernel<<<dim3(HID / 128, MROWS / 128), 256, GEMM_SMEM>>>(
        p_attn, p_wdh, b_dense, out, MROWS, HID, HID);
}

// round 6
// speedup vs baseline: 2.2882x; 1.0401x over previous
#include <cuda_runtime.h>
#include <cuda_fp16.h>
#include <cstdint>
#include <math.h>

// Problem constants
#define BATCH   2
#define SEQ     2048
#define HEADS   16
#define HDIM    128
#define HID     2048
#define NQKV    6144
#define BH      (BATCH * HEADS)      // 32
#define MROWS   (BATCH * SEQ)        // 4096

// scale * log2(e) folded into Q:  (1/sqrt(128)) * 1.4426950408889634
#define QSCALE  0.12751742f

// ---------------------------------------------------------------------------
// Scratch (static device globals; no allocation allowed)
// ---------------------------------------------------------------------------
__device__ __half g_q  [(size_t)BH * SEQ * HDIM];        // 16 MB (fp16, scaled)
__device__ __half g_k  [(size_t)BH * SEQ * HDIM];        // 16 MB
__device__ __half g_v  [(size_t)BH * SEQ * HDIM];        // 16 MB
__device__ __half g_attn[(size_t)MROWS * HID];           // 16 MB (fp16 attn out)
__device__ __half g_hsh [(size_t)MROWS * HID];           // 16 MB (fp16 hs)
__device__ __half g_wqkvh[(size_t)NQKV * HID];           // 24 MB (fp16 w_qkv)
__device__ __half g_wdh [(size_t)HID * HID];             //  8 MB (fp16 w_dense)
__device__ float  g_cos[SEQ * 64];
__device__ float  g_sin[SEQ * 64];

// ---------------------------------------------------------------------------
// PTX helpers
// ---------------------------------------------------------------------------
__device__ __forceinline__ void mma_f16(float c[4], const uint32_t a[4], const uint32_t b[2]) {
    asm volatile(
        "mma.sync.aligned.m16n8k16.row.col.f32.f16.f16.f32 "
        "{%0,%1,%2,%3}, {%4,%5,%6,%7}, {%8,%9}, {%0,%1,%2,%3};\n"
        : "+f"(c[0]), "+f"(c[1]), "+f"(c[2]), "+f"(c[3])
        : "r"(a[0]), "r"(a[1]), "r"(a[2]), "r"(a[3]), "r"(b[0]), "r"(b[1]));
}

__device__ __forceinline__ void ldsm_x4(uint32_t r[4], uint32_t addr) {
    asm volatile("ldmatrix.sync.aligned.m8n8.x4.shared.b16 {%0,%1,%2,%3}, [%4];\n"
                 : "=r"(r[0]), "=r"(r[1]), "=r"(r[2]), "=r"(r[3]) : "r"(addr));
}
__device__ __forceinline__ void ldsm_x4_t(uint32_t r[4], uint32_t addr) {
    asm volatile("ldmatrix.sync.aligned.m8n8.x4.trans.shared.b16 {%0,%1,%2,%3}, [%4];\n"
                 : "=r"(r[0]), "=r"(r[1]), "=r"(r[2]), "=r"(r[3]) : "r"(addr));
}

__device__ __forceinline__ void cp_async16(void* smem_dst, const void* gmem_src) {
    unsigned sa = (unsigned)__cvta_generic_to_shared(smem_dst);
    asm volatile("cp.async.cg.shared.global [%0], [%1], 16;\n" :: "r"(sa), "l"(gmem_src) : "memory");
}
__device__ __forceinline__ void cp_async_commit() {
    asm volatile("cp.async.commit_group;\n" ::: "memory");
}
__device__ __forceinline__ uint32_t packh2(float x, float y) {
    __half2 h = __floats2half2_rn(x, y);
    return *(uint32_t*)&h;
}

// ---------------------------------------------------------------------------
// Kernel: trig tables (fp64 for accuracy at large angles)
// ---------------------------------------------------------------------------
__global__ void trig_init_kernel() {
    int idx = blockIdx.x * blockDim.x + threadIdx.x;   // SEQ*64 total
    if (idx >= SEQ * 64) return;
    int s  = idx >> 6;
    int d2 = idx & 63;
    double inv = exp(-(double)d2 * (9.210340371976184 / 64.0));  // 10000^(-d2/64)
    double ang = (double)s * inv;
    double cs, sn;
    sincos(ang, &sn, &cs);
    g_cos[idx] = (float)cs;
    g_sin[idx] = (float)sn;
}

// ---------------------------------------------------------------------------
// Kernel: elementwise f32 -> fp16 convert (float2 -> half2)
// ---------------------------------------------------------------------------
__global__ __launch_bounds__(256) void cvt_f16_kernel(const float* __restrict__ src,
                                                      __half* __restrict__ dst, int n2) {
    int i = blockIdx.x * blockDim.x + threadIdx.x;
    if (i >= n2) return;
    float2 v = ((const float2*)src)[i];
    ((__half2*)dst)[i] = __floats2half2_rn(v.x, v.y);
}

// ---------------------------------------------------------------------------
// fp16 GEMM:  acc[m,n](f32) = sum_k A[m,k]*B[n,k] + bias[n]
// Tile 128x128x32, 256 threads (8 warps, warp tile 32x64),
// 3-stage cp.async pipeline, ldmatrix fragments, 80B padded rows.
// FUSE=0: C[m,n] = acc (f32, row-major, ld=N)
// FUSE=1: RoPE+scatter epilogue -> g_q/g_k/g_v fp16 (QKV path; C unused)
//         bn tile = one (t,h) slice: t = bn>>4 in {q,k,v}, h = bn&15.
// ---------------------------------------------------------------------------
#define GKS  40                 // halves per smem row
#define GSTG (128 * GKS)        // halves per matrix per stage (5120)
#define OT_S 132                // f32 output-tile row stride (epilogue reuse)
#define GEMM_SMEM (128 * OT_S * 4)   // 67584 B >= 3*2*GSTG*2 (61440)

template<int FUSE>
__global__ __launch_bounds__(256) void gemm_f16_kernel(
    const __half* __restrict__ A, const __half* __restrict__ B,
    const float* __restrict__ bias, float* __restrict__ C,
    int M, int N, int K)
{
    extern __shared__ __half hsm[];
    uint32_t sbase = (uint32_t)__cvta_generic_to_shared(hsm);

    int tid  = threadIdx.x;
    int warp = tid >> 5;
    int lane = tid & 31;
    int bm   = blockIdx.y;
    int bn   = blockIdx.x;
    int wm   = warp >> 1;      // 0..3  (32 rows each)
    int wn   = warp & 1;       // 0..1  (64 cols each)

    const __half* Ab = A + (size_t)bm * 128 * K;
    const __half* Bb = B + (size_t)bn * 128 * K;
    int KT = K / 32;

    auto load_stage = [&](int c, int s) {
        __half* as = hsm + (size_t)s * 2 * GSTG;
        __half* bs = as + GSTG;
        const __half* Ag = Ab + (size_t)c * 32;
        const __half* Bg = Bb + (size_t)c * 32;
        #pragma unroll
        for (int u = 0; u < 2; u++) {
            int t = tid + u * 256;          // 0..511
            int r = t >> 2, ch = (t & 3) * 8;
            cp_async16(as + r * GKS + ch, Ag + (size_t)r * K + ch);
            cp_async16(bs + r * GKS + ch, Bg + (size_t)r * K + ch);
        }
    };

    load_stage(0, 0); cp_async_commit();
    load_stage(1, 1); cp_async_commit();

    float acc[2][8][4];
    #pragma unroll
    for (int i = 0; i < 2; i++)
        #pragma unroll
        for (int j = 0; j < 8; j++)
            #pragma unroll
            for (int k = 0; k < 4; k++) acc[i][j][k] = 0.0f;

    int a_row = (lane & 7) + ((lane >> 3) & 1) * 8;
    int a_k8  = (lane >> 4) * 8;
    int b_row = (lane & 7) + (lane >> 4) * 8;
    int b_k8  = ((lane >> 3) & 1) * 8;

    for (int kt = 0; kt < KT; kt++) {
        asm volatile("cp.async.wait_group 1;\n" ::: "memory");
        __syncthreads();
        if (kt + 2 < KT) load_stage(kt + 2, (kt + 2) % 3);
        cp_async_commit();

        int s = kt % 3;
        uint32_t sa = sbase + (uint32_t)(s * 2 * GSTG) * 2;
        uint32_t sb = sa + GSTG * 2;

        #pragma unroll
        for (int ks2 = 0; ks2 < 2; ks2++) {
            uint32_t af[2][4];
            #pragma unroll
            for (int mt = 0; mt < 2; mt++) {
                uint32_t addr = sa + (uint32_t)(((wm * 32 + mt * 16 + a_row) * GKS
                                  + ks2 * 16 + a_k8) * 2);
                ldsm_x4(af[mt], addr);
            }
            uint32_t bfr[8][2];
            #pragma unroll
            for (int n16 = 0; n16 < 4; n16++) {
                uint32_t r[4];
                uint32_t addr = sb + (uint32_t)(((wn * 64 + n16 * 16 + b_row) * GKS
                                  + ks2 * 16 + b_k8) * 2);
                ldsm_x4(r, addr);
                bfr[n16 * 2][0]     = r[0]; bfr[n16 * 2][1]     = r[1];
                bfr[n16 * 2 + 1][0] = r[2]; bfr[n16 * 2 + 1][1] = r[3];
            }
            #pragma unroll
            for (int mt = 0; mt < 2; mt++)
                #pragma unroll
                for (int nt = 0; nt < 8; nt++)
                    mma_f16(acc[mt][nt], af[mt], bfr[nt]);
        }
    }

    if (FUSE == 0) {
        // plain f32 epilogue
        #pragma unroll
        for (int mt = 0; mt < 2; mt++) {
            int row = bm * 128 + wm * 32 + mt * 16 + (lane >> 2);
            #pragma unroll
            for (int nt = 0; nt < 8; nt++) {
                int col = bn * 128 + wn * 64 + nt * 8 + (lane & 3) * 2;
                float b0 = bias[col], b1 = bias[col + 1];
                C[(size_t)row * N + col]           = acc[mt][nt][0] + b0;
                C[(size_t)row * N + col + 1]       = acc[mt][nt][1] + b1;
                C[(size_t)(row + 8) * N + col]     = acc[mt][nt][2] + b0;
                C[(size_t)(row + 8) * N + col + 1] = acc[mt][nt][3] + b1;
            }
        }
    } else {
        // fused RoPE + scatter epilogue (QKV path)
        __syncthreads();                       // mainloop smem reads done
        float* ot = (float*)hsm;               // reuse pipeline smem as f32 tile
        #pragma unroll
        for (int mt = 0; mt < 2; mt++) {
            int lr = wm * 32 + mt * 16 + (lane >> 2);
            #pragma unroll
            for (int nt = 0; nt < 8; nt++) {
                int lc = wn * 64 + nt * 8 + (lane & 3) * 2;
                float b0 = bias[bn * 128 + lc], b1 = bias[bn * 128 + lc + 1];
                ot[lr * OT_S + lc]           = acc[mt][nt][0] + b0;
                ot[lr * OT_S + lc + 1]       = acc[mt][nt][1] + b1;
                ot[(lr + 8) * OT_S + lc]     = acc[mt][nt][2] + b0;
                ot[(lr + 8) * OT_S + lc + 1] = acc[mt][nt][3] + b1;
            }
        }
        __syncthreads();

        int t = bn >> 4;        // 0=q, 1=k, 2=v
        int h = bn & 15;
        __half* dst = (t == 0) ? g_q : (t == 1) ? g_k : g_v;
        for (int i = tid; i < 128 * 64; i += 256) {
            int r  = i >> 6;
            int d2 = i & 63;
            int gr = bm * 128 + r;
            int b  = gr >> 11;
            int s  = gr & 2047;
            float x1 = ot[r * OT_S + d2];
            float x2 = ot[r * OT_S + d2 + 64];
            float o1, o2;
            if (t == 2) {
                o1 = x1; o2 = x2;
            } else {
                float cs = g_cos[s * 64 + d2];
                float sn = g_sin[s * 64 + d2];
                o1 = x1 * cs - x2 * sn;
                o2 = x2 * cs + x1 * sn;
                if (t == 0) { o1 *= QSCALE; o2 *= QSCALE; }
            }
            size_t o = ((size_t)(b * HEADS + h) * SEQ + s) * HDIM;
            dst[o + d2]      = __float2half_rn(o1);
            dst[o + d2 + 64] = __float2half_rn(o2);
        }
    }
}

// ---------------------------------------------------------------------------
// Causal flash attention: Br=128, Bc=64, 8 warps, fp16 mma m16n8k16
// Q fragments + P registers resident; K via ldmatrix, V via ldmatrix.trans.
// grid = (16 qtiles [reversed], 32 bh), block = 256
// smem (halves): Ks[2][64][136], Vs[2][64][136] = 69632 B
// ---------------------------------------------------------------------------
#define BR 128
#define BC 64
#define KS_H 136
#define KVST_H (64 * KS_H)
#define ATTN_SMEM (4 * KVST_H * 2)

__global__ __launch_bounds__(256, 1) void attn_kernel() {
    extern __shared__ __half smh[];
    uint32_t sb_attn = (uint32_t)__cvta_generic_to_shared(smh);

    int tid  = threadIdx.x;
    int warp = tid >> 5;
    int lane = tid & 31;
    int qi   = gridDim.x - 1 - blockIdx.x;   // big tiles first
    int bh   = blockIdx.y;

    const __half* Qg = g_q + ((size_t)bh * SEQ + (size_t)qi * BR) * HDIM;
    const __half* Kg = g_k + (size_t)bh * SEQ * HDIM;
    const __half* Vg = g_v + (size_t)bh * SEQ * HDIM;

    int r0 = warp * 16 + (lane >> 2);      // local row (c0/c1); c2/c3 -> r0+8
    int kq = (lane & 3) * 2;               // k-pair offset within fragment

    int b_row = (lane & 7) + (lane >> 4) * 8;        // non-trans (K)
    int b_k8  = ((lane >> 3) & 1) * 8;
    int v_mi  = lane >> 3;                           // trans (V): matrix idx
    int v_r   = lane & 7;
    int v_rowoff = (v_mi & 1) * 8 + v_r;             // k-row within 16
    int v_coloff = (v_mi >> 1) * 8;                  // n-col within 16

    // ---- Q fragments to registers (once): 8 ksteps of k16 ----
    uint32_t qf[8][4];
    #pragma unroll
    for (int ks = 0; ks < 8; ks++) {
        int kb = ks * 16 + kq;
        qf[ks][0] = __ldg((const uint32_t*)(Qg + (size_t)r0 * HDIM + kb));
        qf[ks][1] = __ldg((const uint32_t*)(Qg + (size_t)(r0 + 8) * HDIM + kb));
        qf[ks][2] = __ldg((const uint32_t*)(Qg + (size_t)r0 * HDIM + kb + 8));
        qf[ks][3] = __ldg((const uint32_t*)(Qg + (size_t)(r0 + 8) * HDIM + kb + 8));
    }

    int ktmax = 2 * qi + 1;

    // prologue: tile 0 -> buffer 0
    {
        __half* kd = smh;
        __half* vd = smh + 2 * KVST_H;
        for (int i = tid; i < 1024; i += 256) {
            int r = i >> 4;
            int c = (i & 15) * 8;
            cp_async16(kd + r * KS_H + c, Kg + (size_t)r * HDIM + c);
            cp_async16(vd + r * KS_H + c, Vg + (size_t)r * HDIM + c);
        }
        cp_async_commit();
    }

    float m0 = -1e30f, m1 = -1e30f;
    float l0 = 0.0f,   l1 = 0.0f;
    float acc[16][4];
    #pragma unroll
    for (int i = 0; i < 16; i++)
        #pragma unroll
        for (int j = 0; j < 4; j++) acc[i][j] = 0.0f;

    for (int kt = 0; kt <= ktmax; kt++) {
        int cur = kt & 1;
        if (kt < ktmax) {
            int nb = cur ^ 1;
            const __half* kp = Kg + (size_t)(kt + 1) * BC * HDIM;
            const __half* vp = Vg + (size_t)(kt + 1) * BC * HDIM;
            __half* kd = smh + (size_t)nb * KVST_H;
            __half* vd = smh + (size_t)(2 + nb) * KVST_H;
            for (int i = tid; i < 1024; i += 256) {
                int r = i >> 4;
                int c = (i & 15) * 8;
                cp_async16(kd + r * KS_H + c, kp + (size_t)r * HDIM + c);
                cp_async16(vd + r * KS_H + c, vp + (size_t)r * HDIM + c);
            }
            cp_async_commit();
            asm volatile("cp.async.wait_group 1;\n" ::: "memory");
        } else {
            asm volatile("cp.async.wait_group 0;\n" ::: "memory");
        }
        __syncthreads();

        uint32_t kbase = sb_attn + (uint32_t)(cur * KVST_H) * 2;
        uint32_t vbase = sb_attn + (uint32_t)((2 + cur) * KVST_H) * 2;

        // ---- S = Q K^T (16x64 per warp): K via ldmatrix.x4 ----
        float sc[8][4];
        #pragma unroll
        for (int nt = 0; nt < 8; nt++)
            #pragma unroll
            for (int j = 0; j < 4; j++) sc[nt][j] = 0.0f;

        #pragma unroll
        for (int ks = 0; ks < 8; ks++) {
            #pragma unroll
            for (int n16 = 0; n16 < 4; n16++) {
                uint32_t r[4];
                uint32_t addr = kbase + (uint32_t)(((n16 * 16 + b_row) * KS_H
                                  + ks * 16 + b_k8) * 2);
                ldsm_x4(r, addr);
                uint32_t bf0[2] = {r[0], r[1]};
                uint32_t bf1[2] = {r[2], r[3]};
                mma_f16(sc[n16 * 2],     qf[ks], bf0);
                mma_f16(sc[n16 * 2 + 1], qf[ks], bf1);
            }
        }

        // ---- causal mask (only tiles touching the diagonal) ----
        if (kt >= 2 * qi) {
            int grow0 = qi * BR + r0;
            #pragma unroll
            for (int nt = 0; nt < 8; nt++) {
                int cg = kt * BC + nt * 8 + (lane & 3) * 2;
                if (cg     > grow0)     sc[nt][0] = -1e30f;
                if (cg + 1 > grow0)     sc[nt][1] = -1e30f;
                if (cg     > grow0 + 8) sc[nt][2] = -1e30f;
                if (cg + 1 > grow0 + 8) sc[nt][3] = -1e30f;
            }
        }

        // ---- online softmax (base-2, scale folded into Q) ----
        float rx0 = -1e30f, rx1 = -1e30f;
        #pragma unroll
        for (int nt = 0; nt < 8; nt++) {
            rx0 = fmaxf(rx0, fmaxf(sc[nt][0], sc[nt][1]));
            rx1 = fmaxf(rx1, fmaxf(sc[nt][2], sc[nt][3]));
        }
        rx0 = fmaxf(rx0, __shfl_xor_sync(0xffffffffu, rx0, 1));
        rx0 = fmaxf(rx0, __shfl_xor_sync(0xffffffffu, rx0, 2));
        rx1 = fmaxf(rx1, __shfl_xor_sync(0xffffffffu, rx1, 1));
        rx1 = fmaxf(rx1, __shfl_xor_sync(0xffffffffu, rx1, 2));

        float mn0 = fmaxf(m0, rx0);
        float mn1 = fmaxf(m1, rx1);
        float al0 = exp2f(m0 - mn0);
        float al1 = exp2f(m1 - mn1);

        float s0 = 0.0f, s1 = 0.0f;
        #pragma unroll
        for (int nt = 0; nt < 8; nt++) {
            sc[nt][0] = exp2f(sc[nt][0] - mn0);
            sc[nt][1] = exp2f(sc[nt][1] - mn0);
            sc[nt][2] = exp2f(sc[nt][2] - mn1);
            sc[nt][3] = exp2f(sc[nt][3] - mn1);
            s0 += sc[nt][0] + sc[nt][1];
            s1 += sc[nt][2] + sc[nt][3];
        }
        s0 += __shfl_xor_sync(0xffffffffu, s0, 1);
        s0 += __shfl_xor_sync(0xffffffffu, s0, 2);
        s1 += __shfl_xor_sync(0xffffffffu, s1, 1);
        s1 += __shfl_xor_sync(0xffffffffu, s1, 2);

        l0 = l0 * al0 + s0;
        l1 = l1 * al1 + s1;
        m0 = mn0;
        m1 = mn1;

        #pragma unroll
        for (int nt = 0; nt < 16; nt++) {
            acc[nt][0] *= al0; acc[nt][1] *= al0;
            acc[nt][2] *= al1; acc[nt][3] *= al1;
        }

        // ---- P -> A fragments in registers (no smem roundtrip) ----
        uint32_t pf[4][4];
        #pragma unroll
        for (int ks = 0; ks < 4; ks++) {
            pf[ks][0] = packh2(sc[2*ks][0],     sc[2*ks][1]);
            pf[ks][1] = packh2(sc[2*ks][2],     sc[2*ks][3]);
            pf[ks][2] = packh2(sc[2*ks + 1][0], sc[2*ks + 1][1]);
            pf[ks][3] = packh2(sc[2*ks + 1][2], sc[2*ks + 1][3]);
        }

        // ---- O += P @ V : V via ldmatrix.x4.trans ----
        #pragma unroll
        for (int ks = 0; ks < 4; ks++) {
            #pragma unroll
            for (int n16 = 0; n16 < 8; n16++) {
                uint32_t r[4];
                uint32_t addr = vbase + (uint32_t)(((ks * 16 + v_rowoff) * KS_H
                                  + n16 * 16 + v_coloff) * 2);
                ldsm_x4_t(r, addr);
                uint32_t bf0[2] = {r[0], r[1]};
                uint32_t bf1[2] = {r[2], r[3]};
                mma_f16(acc[n16 * 2],     pf[ks], bf0);
                mma_f16(acc[n16 * 2 + 1], pf[ks], bf1);
            }
        }
        __syncthreads();
    }

    // epilogue: normalize, convert fp16 (dense GEMM input), write [B,S,HID]
    float inv0 = 1.0f / l0;
    float inv1 = 1.0f / l1;
    int b = bh >> 4;
    int h = bh & 15;
    size_t rowg = (size_t)b * SEQ + (size_t)qi * BR + r0;
    __half* out0 = g_attn + rowg * HID + (size_t)h * HDIM;
    __half* out1 = out0 + (size_t)8 * HID;
    #pragma unroll
    for (int nt = 0; nt < 16; nt++) {
        int c = nt * 8 + (lane & 3) * 2;
        *(__half2*)(out0 + c) = __floats2half2_rn(acc[nt][0] * inv0, acc[nt][1] * inv0);
        *(__half2*)(out1 + c) = __floats2half2_rn(acc[nt][2] * inv1, acc[nt][3] * inv1);
    }
}

// ---------------------------------------------------------------------------
// Host launcher
// ---------------------------------------------------------------------------
extern "C" void kernel_launch(void* const* d_in, const int* in_sizes, int n_in,
                              void* d_out, int out_size)
{
    const float* hs      = (const float*)d_in[0];
    const float* w_qkv   = (const float*)d_in[1];
    const float* b_qkv   = (const float*)d_in[2];
    const float* w_dense = (const float*)d_in[3];
    const float* b_dense = (const float*)d_in[4];
    float* out = (float*)d_out;

    __half *p_attn, *p_hsh, *p_wqkvh, *p_wdh;
    cudaGetSymbolAddress((void**)&p_attn,  g_attn);
    cudaGetSymbolAddress((void**)&p_hsh,   g_hsh);
    cudaGetSymbolAddress((void**)&p_wqkvh, g_wqkvh);
    cudaGetSymbolAddress((void**)&p_wdh,   g_wdh);

    cudaFuncSetAttribute(gemm_f16_kernel<0>, cudaFuncAttributeMaxDynamicSharedMemorySize, GEMM_SMEM);
    cudaFuncSetAttribute(gemm_f16_kernel<1>, cudaFuncAttributeMaxDynamicSharedMemorySize, GEMM_SMEM);
    cudaFuncSetAttribute(attn_kernel,        cudaFuncAttributeMaxDynamicSharedMemorySize, ATTN_SMEM);

    // 0) trig tables + fp16 conversion of GEMM inputs
    trig_init_kernel<<<(SEQ * 64 + 255) / 256, 256>>>();
    cvt_f16_kernel<<<(MROWS * HID / 2 + 255) / 256, 256>>>(hs, p_hsh, MROWS * HID / 2);
    cvt_f16_kernel<<<(NQKV * HID / 2 + 255) / 256, 256>>>(w_qkv, p_wqkvh, NQKV * HID / 2);
    cvt_f16_kernel<<<(HID * HID / 2 + 255) / 256, 256>>>(w_dense, p_wdh, HID * HID / 2);

    // 1) QKV GEMM + fused RoPE/scatter -> g_q/g_k/g_v (fp16)
    gemm_f16_kernel<1><<<dim3(NQKV / 128, MROWS / 128), 256, GEMM_SMEM>>>(
        p_hsh, p_wqkvh, b_qkv, nullptr, MROWS, NQKV, HID);

    // 2) causal flash attention (fp16 mma)
    attn_kernel<<<dim3(SEQ / BR, BH), 256, ATTN_SMEM>>>();

    // 3) dense GEMM (fp16 in, f32 out): [4096,2048] x [2048,2048]^T -> [4096,2048]
    gemm_f16_kernel<0><<<dim3(HID / 128, MROWS / 128), 256, GEMM_SMEM>>>(
        p_attn, p_wdh, b_dense, out, MROWS, HID, HID);
}